// round 4
// baseline (speedup 1.0000x reference)
#include <cuda_runtime.h>

// ---------------- problem constants ----------------
#define BSZ   8
#define NC    128
#define TD    512
#define EDIM  64
#define NE    128
#define NTOK  (BSZ*NC)     // 1024 tokens
#define T2    (2*TD)       // 1024 concat dim

// ---------------- GEMM tiling ----------------
#define BN 128             // n-columns per CTA
#define NT (TD/BN)         // 4 n-tiles
#define KC 32              // k-tile (double buffered)
#define MC 16              // m rows per pass
#define NKT (TD/KC)        // 16 k-tiles

// ---------------- device scratch (no allocation allowed) ----------------
__device__ int   g_cnt[NE];
__device__ int   g_list[NE][NTOK];          // packed token*2 + slot
__device__ float g_part[4][NTOK][TD];       // [slot*2+stream][token][t]  (8 MB)

// ---------------- f32x2 packed-FMA helpers ----------------
__device__ __forceinline__ unsigned long long fma2(unsigned long long a,
                                                   unsigned long long b,
                                                   unsigned long long c) {
    unsigned long long d;
    asm("fma.rn.f32x2 %0, %1, %2, %3;" : "=l"(d) : "l"(a), "l"(b), "l"(c));
    return d;
}
__device__ __forceinline__ unsigned long long pack2(float lo, float hi) {
    unsigned long long d;
    asm("mov.b64 %0, {%1, %2};" : "=l"(d) : "f"(lo), "f"(hi));
    return d;
}
__device__ __forceinline__ float2 unpack2(unsigned long long v) {
    float2 r;
    asm("mov.b64 {%0, %1}, %2;" : "=f"(r.x), "=f"(r.y) : "l"(v));
    return r;
}

// ---------------- kernel 0: zero per-expert counters ----------------
__global__ void zero_cnt_kernel() { g_cnt[threadIdx.x] = 0; }

// ---------------- kernel 1: router (top-2 expert indices per token) -----
// s_e = (x @ projW^T + projb) . centers[e]/||centers[e]||
// x_proj L2-norm is a positive per-token scalar (order-preserving) and the
// reference's token-level mask makes each selected expert's combine weight
// exactly 1.0, so only the top-2 indices matter.
__global__ __launch_bounds__(256) void router_kernel(
    const float* __restrict__ x_l, const float* __restrict__ x_r,
    const float* __restrict__ centers,
    const float* __restrict__ projW, const float* __restrict__ projb)
{
    __shared__ float xs[T2];
    __shared__ float ps[EDIM];
    __shared__ float ss[NE];
    int tok = blockIdx.x;
    int tid = threadIdx.x;
    const float* xl = x_l + (size_t)tok * TD;
    const float* xr = x_r + (size_t)tok * TD;
    for (int i = tid; i < TD; i += 256) { xs[i] = xl[i]; xs[i + TD] = xr[i]; }
    __syncthreads();

    int warp = tid >> 5, lane = tid & 31;
    for (int it = 0; it < 8; ++it) {
        int j = warp + 8 * it;
        const float* w = projW + (size_t)j * T2;
        float s = 0.f;
        #pragma unroll 4
        for (int k = lane; k < T2; k += 32) s += xs[k] * w[k];
        #pragma unroll
        for (int o = 16; o; o >>= 1) s += __shfl_xor_sync(0xffffffffu, s, o);
        if (lane == 0) ps[j] = s + projb[j];
    }
    __syncthreads();

    if (tid < NE) {
        const float* c = centers + (size_t)tid * EDIM;
        float s = 0.f, n = 0.f;
        #pragma unroll 8
        for (int j = 0; j < EDIM; ++j) { float cv = c[j]; s += ps[j] * cv; n += cv * cv; }
        ss[tid] = s * rsqrtf(fmaxf(n, 1e-24f));
    }
    __syncthreads();

    if (tid == 0) {
        // strict > keeps first-index tie-break, matching jax.lax.top_k
        int e0 = 0; float b0 = ss[0];
        for (int e = 1; e < NE; ++e) if (ss[e] > b0) { b0 = ss[e]; e0 = e; }
        int e1 = (e0 == 0) ? 1 : 0; float b1 = ss[e1];
        for (int e = 0; e < NE; ++e) if (e != e0 && ss[e] > b1) { b1 = ss[e]; e1 = e; }
        int p0 = atomicAdd(&g_cnt[e0], 1);
        g_list[e0][p0] = tok * 2 + 0;
        int p1 = atomicAdd(&g_cnt[e1], 1);
        g_list[e1][p1] = tok * 2 + 1;
    }
}

// ---------------- kernel 2: grouped per-expert GEMM (double-buffered) ----
// CTA (e, nt): out[row][n] = x_row . We[n][:] + be[n], n in [nt*BN, +BN)
// f32x2 inner loop: per k per thread 16 lane-FMA in 4 FFMA2.
__global__ __launch_bounds__(256) void expert_gemm_kernel(
    const float* __restrict__ x_l, const float* __restrict__ x_r,
    const float* __restrict__ eW,  const float* __restrict__ eB)
{
    __shared__ float Ws[2][KC][BN + 4];   // 2 x 32 x 132 floats = 33.8 KB
    __shared__ float xsm[2][KC][MC + 2];  // 2 x 32 x 18 floats  =  4.6 KB

    int e = blockIdx.x, nt = blockIdx.y;
    int cnt = g_cnt[e];
    int rows = 2 * cnt;
    if (rows == 0) return;

    int tid  = threadIdx.x;
    int lane = tid & 31;
    int n0l  = lane * 4;               // 0..124 (per-warp n quad)
    int m0   = (tid >> 5) * 2;         // 0..14  (per-warp m pair)
    int N0   = nt * BN;
    const float* We = eW + (size_t)e * TD * TD + (size_t)N0 * TD;
    float4 bias = *reinterpret_cast<const float4*>(eB + (size_t)e * TD + N0 + n0l);

    // W loader: thread -> row n_w, half kbase; 4 float4 = 16 consecutive k
    int n_w   = tid & 127;
    int kbase = (tid >> 7) * 16;
    const float* wsrc = We + (size_t)n_w * TD + kbase;
    // x loader: thread -> row m_x, 2 consecutive k at kx
    int m_x = tid & 15;
    int kx  = (tid >> 4) * 2;

    for (int mp = 0; mp < rows; mp += MC) {
        // ---- per-pass row metadata for compute (m0, m0+1) ----
        int tokm[2], strm[2], slotm[2], valm[2];
        #pragma unroll
        for (int i = 0; i < 2; ++i) {
            int r = mp + m0 + i;
            valm[i] = (r < rows);
            int rr = valm[i] ? r : 0;
            int entry = (rr < cnt) ? rr : rr - cnt;
            strm[i] = (rr < cnt) ? 0 : 1;
            int packed = g_list[e][entry];
            tokm[i]  = packed >> 1;
            slotm[i] = packed & 1;
        }
        // ---- x loader row pointer ----
        const float* xsrc = nullptr;
        {
            int lr = mp + m_x;
            if (lr < rows) {
                int entry = (lr < cnt) ? lr : lr - cnt;
                const float* base = (lr < cnt) ? x_l : x_r;
                xsrc = base + (size_t)(g_list[e][entry] >> 1) * TD;
            }
        }

        unsigned long long a00 = 0ull, a01 = 0ull, a10 = 0ull, a11 = 0ull;

        // ---- prologue: stage tile 0 and commit to buffer 0 ----
        float4 wreg[4];
        float2 xreg;
        #pragma unroll
        for (int i = 0; i < 4; ++i)
            wreg[i] = *reinterpret_cast<const float4*>(wsrc + i * 4);
        xreg = xsrc ? *reinterpret_cast<const float2*>(xsrc + kx)
                    : make_float2(0.f, 0.f);
        #pragma unroll
        for (int i = 0; i < 4; ++i) {
            Ws[0][kbase + i * 4 + 0][n_w] = wreg[i].x;
            Ws[0][kbase + i * 4 + 1][n_w] = wreg[i].y;
            Ws[0][kbase + i * 4 + 2][n_w] = wreg[i].z;
            Ws[0][kbase + i * 4 + 3][n_w] = wreg[i].w;
        }
        xsm[0][kx + 0][m_x] = xreg.x;
        xsm[0][kx + 1][m_x] = xreg.y;
        __syncthreads();

        for (int kt = 0; kt < NKT; ++kt) {
            int p = kt & 1;
            // stage next tile from GMEM (overlaps with compute below)
            if (kt + 1 < NKT) {
                const float* ws = wsrc + (kt + 1) * KC;
                #pragma unroll
                for (int i = 0; i < 4; ++i)
                    wreg[i] = *reinterpret_cast<const float4*>(ws + i * 4);
                xreg = xsrc ? *reinterpret_cast<const float2*>(xsrc + (kt + 1) * KC + kx)
                            : make_float2(0.f, 0.f);
            }
            // compute current tile
            #pragma unroll
            for (int k = 0; k < KC; ++k) {
                ulonglong2 w = *reinterpret_cast<const ulonglong2*>(&Ws[p][k][n0l]);
                float2 xv = *reinterpret_cast<const float2*>(&xsm[p][k][m0]);
                unsigned long long xd0 = pack2(xv.x, xv.x);
                unsigned long long xd1 = pack2(xv.y, xv.y);
                a00 = fma2(w.x, xd0, a00);
                a01 = fma2(w.x, xd1, a01);
                a10 = fma2(w.y, xd0, a10);
                a11 = fma2(w.y, xd1, a11);
            }
            // commit staged tile to the other buffer
            if (kt + 1 < NKT) {
                int q = p ^ 1;
                #pragma unroll
                for (int i = 0; i < 4; ++i) {
                    Ws[q][kbase + i * 4 + 0][n_w] = wreg[i].x;
                    Ws[q][kbase + i * 4 + 1][n_w] = wreg[i].y;
                    Ws[q][kbase + i * 4 + 2][n_w] = wreg[i].z;
                    Ws[q][kbase + i * 4 + 3][n_w] = wreg[i].w;
                }
                xsm[q][kx + 0][m_x] = xreg.x;
                xsm[q][kx + 1][m_x] = xreg.y;
            }
            __syncthreads();
        }

        // ---- epilogue: float4 STG per valid m row (unique dest, no atomics) ----
        #pragma unroll
        for (int i = 0; i < 2; ++i) {
            float2 lo = unpack2(i ? a01 : a00);   // (n0, n1)
            float2 hi = unpack2(i ? a11 : a10);   // (n2, n3)
            float4 o;
            o.x = lo.x + bias.x;
            o.y = lo.y + bias.y;
            o.z = hi.x + bias.z;
            o.w = hi.y + bias.w;
            float* dst = &g_part[slotm[i] * 2 + strm[i]][tokm[i]][N0 + n0l];
            if (valm[i]) *reinterpret_cast<float4*>(dst) = o;
        }
    }
}

// ---------------- kernel 3: combine slots + LayerNorm + residual --------
__global__ __launch_bounds__(128) void ln_kernel(
    const float* __restrict__ x_l, const float* __restrict__ x_r,
    const float* __restrict__ lw_l, const float* __restrict__ lb_l,
    const float* __restrict__ lw_r, const float* __restrict__ lb_r,
    float* __restrict__ out)
{
    __shared__ float red[8];
    int bid = blockIdx.x;
    int stream = bid >> 10;            // NTOK = 1024
    int tok = bid & (NTOK - 1);
    int tid = threadIdx.x;

    const float* p0 = g_part[0 * 2 + stream][tok];
    const float* p1 = g_part[1 * 2 + stream][tok];
    const float* xr = (stream ? x_r : x_l) + (size_t)tok * TD;
    const float* w  = stream ? lw_r : lw_l;
    const float* b  = stream ? lb_r : lb_l;

    int base = tid * 4;
    float4 a = *reinterpret_cast<const float4*>(p0 + base);
    float4 c = *reinterpret_cast<const float4*>(p1 + base);
    float v0 = a.x + c.x, v1 = a.y + c.y, v2 = a.z + c.z, v3 = a.w + c.w;
    float s1 = v0 + v1 + v2 + v3;
    float s2 = v0 * v0 + v1 * v1 + v2 * v2 + v3 * v3;
    #pragma unroll
    for (int o = 16; o; o >>= 1) {
        s1 += __shfl_xor_sync(0xffffffffu, s1, o);
        s2 += __shfl_xor_sync(0xffffffffu, s2, o);
    }
    int warp = tid >> 5, lane = tid & 31;
    if (lane == 0) { red[warp] = s1; red[4 + warp] = s2; }
    __syncthreads();
    float S1 = red[0] + red[1] + red[2] + red[3];
    float S2 = red[4] + red[5] + red[6] + red[7];
    float mu  = S1 * (1.f / TD);
    float var = S2 * (1.f / TD) - mu * mu;
    float rs  = rsqrtf(fmaxf(var, 0.f) + 1e-5f);

    float4 wv = *reinterpret_cast<const float4*>(w + base);
    float4 bv = *reinterpret_cast<const float4*>(b + base);
    float4 xv = *reinterpret_cast<const float4*>(xr + base);
    float4 o;
    o.x = (v0 - mu) * rs * wv.x + bv.x + xv.x;
    o.y = (v1 - mu) * rs * wv.y + bv.y + xv.y;
    o.z = (v2 - mu) * rs * wv.z + bv.z + xv.z;
    o.w = (v3 - mu) * rs * wv.w + bv.w + xv.w;
    *reinterpret_cast<float4*>(out + (size_t)stream * NTOK * TD + (size_t)tok * TD + base) = o;
}

// ---------------- launch ----------------
extern "C" void kernel_launch(void* const* d_in, const int* in_sizes, int n_in,
                              void* d_out, int out_size)
{
    const float* x_l   = (const float*)d_in[0];
    const float* x_r   = (const float*)d_in[1];
    const float* cent  = (const float*)d_in[2];
    const float* projW = (const float*)d_in[3];
    const float* projb = (const float*)d_in[4];
    const float* eW    = (const float*)d_in[5];
    const float* eB    = (const float*)d_in[6];
    const float* lwl   = (const float*)d_in[7];
    const float* lbl   = (const float*)d_in[8];
    const float* lwr   = (const float*)d_in[9];
    const float* lbr   = (const float*)d_in[10];
    float* out = (float*)d_out;

    zero_cnt_kernel<<<1, NE>>>();
    router_kernel<<<NTOK, 256>>>(x_l, x_r, cent, projW, projb);
    dim3 g(NE, NT);
    expert_gemm_kernel<<<g, 256>>>(x_l, x_r, eW, eB);
    ln_kernel<<<2 * NTOK, 128>>>(x_l, x_r, lwl, lbl, lwr, lbr, out);
}

// round 5
// speedup vs baseline: 1.1232x; 1.1232x over previous
#include <cuda_runtime.h>

// ---------------- problem constants ----------------
#define BSZ   8
#define NC    128
#define TD    512
#define EDIM  64
#define NE    128
#define NTOK  (BSZ*NC)     // 1024 tokens
#define T2    (2*TD)       // 1024 concat dim

// ---------------- GEMM tiling ----------------
#define BN 128             // n-columns per CTA
#define NT (TD/BN)         // 4 n-tiles
#define KC 64              // k-tile
#define MC 32              // m rows per pass
#define NKT (TD/KC)        // 8 k-tiles
#define XP 36              // x smem row pitch (floats)

// ---------------- device scratch (no allocation allowed) ----------------
__device__ int   g_cnt[NE];
__device__ int   g_list[NE][NTOK];          // packed token*2 + slot
__device__ float g_part[4][NTOK][TD];       // [slot*2+stream][token][t]  (8 MB)

// ---------------- f32x2 packed-FMA helpers ----------------
__device__ __forceinline__ unsigned long long fma2(unsigned long long a,
                                                   unsigned long long b,
                                                   unsigned long long c) {
    unsigned long long d;
    asm("fma.rn.f32x2 %0, %1, %2, %3;" : "=l"(d) : "l"(a), "l"(b), "l"(c));
    return d;
}
__device__ __forceinline__ unsigned long long pack2(float lo, float hi) {
    unsigned long long d;
    asm("mov.b64 %0, {%1, %2};" : "=l"(d) : "f"(lo), "f"(hi));
    return d;
}
__device__ __forceinline__ float2 unpack2(unsigned long long v) {
    float2 r;
    asm("mov.b64 {%0, %1}, %2;" : "=f"(r.x), "=f"(r.y) : "l"(v));
    return r;
}

// ---------------- kernel 0: zero per-expert counters ----------------
__global__ void zero_cnt_kernel() { g_cnt[threadIdx.x] = 0; }

// ---------------- kernel 1: router, 4 tokens per CTA ----------------
// s_e = (x @ projW^T + projb) . centers[e]/||centers[e]||
// x_proj L2-norm is a positive per-token scalar (order-preserving) and the
// reference's token-level mask makes each selected expert's combine weight
// exactly softmax(p0)+softmax(p1) = 1.0, so only top-2 indices matter.
#define TPC 4
__global__ __launch_bounds__(256) void router_kernel(
    const float* __restrict__ x_l, const float* __restrict__ x_r,
    const float* __restrict__ centers,
    const float* __restrict__ projW, const float* __restrict__ projb)
{
    __shared__ float xs[TPC][T2];     // 16 KB
    __shared__ float ps[TPC][EDIM];   // 1 KB
    __shared__ float ss[TPC][NE];     // 2 KB
    int tok0 = blockIdx.x * TPC;
    int tid = threadIdx.x;

    #pragma unroll
    for (int t = 0; t < TPC; ++t) {
        const float* xl = x_l + (size_t)(tok0 + t) * TD;
        const float* xr = x_r + (size_t)(tok0 + t) * TD;
        for (int i = tid; i < TD; i += 256) { xs[t][i] = xl[i]; xs[t][i + TD] = xr[i]; }
    }
    __syncthreads();

    int warp = tid >> 5, lane = tid & 31;
    int t_w = warp >> 1;               // token handled by this warp (2 warps/token)
    int jbase = (warp & 1) * 32;       // j half
    for (int it = 0; it < 32; ++it) {
        int j = jbase + it;
        const float* w = projW + (size_t)j * T2;
        float s = 0.f;
        #pragma unroll 4
        for (int k = lane; k < T2; k += 32) s += xs[t_w][k] * w[k];
        #pragma unroll
        for (int o = 16; o; o >>= 1) s += __shfl_xor_sync(0xffffffffu, s, o);
        if (lane == 0) ps[t_w][j] = s + projb[j];
    }
    __syncthreads();

    // 512 (token, expert) scores over 256 threads, 2 rounds
    #pragma unroll
    for (int r = 0; r < 2; ++r) {
        int idx = tid + 256 * r;
        int t = idx >> 7, e = idx & 127;
        const float* c = centers + (size_t)e * EDIM;
        float s = 0.f, n = 0.f;
        #pragma unroll 8
        for (int j = 0; j < EDIM; ++j) { float cv = c[j]; s += ps[t][j] * cv; n += cv * cv; }
        ss[t][e] = s * rsqrtf(fmaxf(n, 1e-24f));
    }
    __syncthreads();

    if (tid < TPC) {
        int t = tid, tok = tok0 + t;
        // strict > keeps first-index tie-break, matching jax.lax.top_k
        int e0 = 0; float b0 = ss[t][0];
        for (int e = 1; e < NE; ++e) if (ss[t][e] > b0) { b0 = ss[t][e]; e0 = e; }
        int e1 = (e0 == 0) ? 1 : 0; float b1 = ss[t][e1];
        for (int e = 0; e < NE; ++e) if (e != e0 && ss[t][e] > b1) { b1 = ss[t][e]; e1 = e; }
        int p0 = atomicAdd(&g_cnt[e0], 1);
        g_list[e0][p0] = tok * 2 + 0;
        int p1 = atomicAdd(&g_cnt[e1], 1);
        g_list[e1][p1] = tok * 2 + 1;
    }
}

// ---------------- kernel 2: grouped per-expert GEMM ----------------
// CTA (e, nt): out[row][n] = x_row . We[n][:] + be[n], n in [nt*BN, +BN)
// W smem: transposed [k][n] with XOR quad swizzle -> conflict-free LDS.128
// reads AND ~2-way STS. W LDG fully coalesced (16 lanes along k => nL=4).
__global__ __launch_bounds__(256) void expert_gemm_kernel(
    const float* __restrict__ x_l, const float* __restrict__ x_r,
    const float* __restrict__ eW,  const float* __restrict__ eB)
{
    __shared__ float Wst[KC * BN];     // 32 KB, phys = k*128 + 4*(quad^(k&31)) + sub
    __shared__ float xst[KC * XP];     // 9 KB,  x[k][m] at k*XP + m

    int e = blockIdx.x, nt = blockIdx.y;
    int cnt = g_cnt[e];
    int rows = 2 * cnt;
    if (rows == 0) return;

    int tid  = threadIdx.x;
    int lane = tid & 31;
    int warp = tid >> 5;
    int m0   = warp * 4;               // warp-uniform m quad
    int N0   = nt * BN;
    const float* We = eW + (size_t)e * TD * TD + (size_t)N0 * TD;
    float4 bias = *reinterpret_cast<const float4*>(eB + (size_t)e * TD + N0 + lane * 4);

    // W loader: 16 lanes along k of one row (coalesced), 8 rows per thread
    int wk4 = (tid & 15) * 4;          // 0..60
    int wn  = tid >> 4;                // 0..15 (+16*i)
    // x loader: 8 lanes along k of one gathered row
    int xk8 = (tid & 7) * 8;           // 0..56
    int xm  = tid >> 3;                // 0..31

    for (int mp = 0; mp < rows; mp += MC) {
        // per-warp m metadata (broadcast loads)
        int tokm[4], strm[4], slotm[4], valm[4];
        #pragma unroll
        for (int i = 0; i < 4; ++i) {
            int r = mp + m0 + i;
            valm[i] = (r < rows);
            int rr = valm[i] ? r : 0;
            int entry = (rr < cnt) ? rr : rr - cnt;
            strm[i] = (rr < cnt) ? 0 : 1;
            int packed = g_list[e][entry];
            tokm[i]  = packed >> 1;
            slotm[i] = packed & 1;
        }
        // x loader row pointer
        const float* xsrc = nullptr;
        {
            int lr = mp + xm;
            if (lr < rows) {
                int entry = (lr < cnt) ? lr : lr - cnt;
                const float* base = (lr < cnt) ? x_l : x_r;
                xsrc = base + (size_t)(g_list[e][entry] >> 1) * TD;
            }
        }

        unsigned long long acc[2][4];  // [n-pair][m]
        #pragma unroll
        for (int p = 0; p < 2; ++p)
            #pragma unroll
            for (int m = 0; m < 4; ++m) acc[p][m] = 0ull;

        for (int kt = 0; kt < NKT; ++kt) {
            int k0 = kt * KC;
            __syncthreads();
            // ---- W tile: 8 coalesced float4 LDG -> swizzled transposed STS ----
            #pragma unroll
            for (int i = 0; i < 8; ++i) {
                int n = wn + 16 * i;
                float4 v = *reinterpret_cast<const float4*>(We + (size_t)n * TD + k0 + wk4);
                int q = n >> 2, sub = n & 3;
                float va[4] = {v.x, v.y, v.z, v.w};
                #pragma unroll
                for (int j = 0; j < 4; ++j) {
                    int kk = wk4 + j;
                    Wst[kk * BN + ((q ^ (kk & 31)) << 2) + sub] = va[j];
                }
            }
            // ---- x tile: 2 float4 LDG -> transposed STS ----
            #pragma unroll
            for (int i = 0; i < 2; ++i) {
                float4 v = xsrc ? *reinterpret_cast<const float4*>(xsrc + k0 + xk8 + i * 4)
                                : make_float4(0.f, 0.f, 0.f, 0.f);
                int kk = xk8 + i * 4;
                xst[(kk + 0) * XP + xm] = v.x;
                xst[(kk + 1) * XP + xm] = v.y;
                xst[(kk + 2) * XP + xm] = v.z;
                xst[(kk + 3) * XP + xm] = v.w;
            }
            __syncthreads();
            // ---- compute: per k: 1 swizzled W LDS.128 + 1 bcast x LDS.128 ----
            #pragma unroll
            for (int k = 0; k < KC; ++k) {
                ulonglong2 w = *reinterpret_cast<const ulonglong2*>(
                    &Wst[k * BN + (((lane ^ (k & 31)) & 31) << 2)]);
                float4 xv = *reinterpret_cast<const float4*>(&xst[k * XP + m0]);
                unsigned long long xd0 = pack2(xv.x, xv.x);
                unsigned long long xd1 = pack2(xv.y, xv.y);
                unsigned long long xd2 = pack2(xv.z, xv.z);
                unsigned long long xd3 = pack2(xv.w, xv.w);
                acc[0][0] = fma2(w.x, xd0, acc[0][0]);
                acc[1][0] = fma2(w.y, xd0, acc[1][0]);
                acc[0][1] = fma2(w.x, xd1, acc[0][1]);
                acc[1][1] = fma2(w.y, xd1, acc[1][1]);
                acc[0][2] = fma2(w.x, xd2, acc[0][2]);
                acc[1][2] = fma2(w.y, xd2, acc[1][2]);
                acc[0][3] = fma2(w.x, xd3, acc[0][3]);
                acc[1][3] = fma2(w.y, xd3, acc[1][3]);
            }
        }

        // ---- epilogue: one float4 STG per valid m row (unique dest) ----
        #pragma unroll
        for (int i = 0; i < 4; ++i) {
            float2 lo = unpack2(acc[0][i]);   // (n0, n1)
            float2 hi = unpack2(acc[1][i]);   // (n2, n3)
            float4 o;
            o.x = lo.x + bias.x;
            o.y = lo.y + bias.y;
            o.z = hi.x + bias.z;
            o.w = hi.y + bias.w;
            float* dst = &g_part[slotm[i] * 2 + strm[i]][tokm[i]][N0 + lane * 4];
            if (valm[i]) *reinterpret_cast<float4*>(dst) = o;
        }
        __syncthreads();
    }
}

// ---------------- kernel 3: combine slots + LayerNorm + residual --------
__global__ __launch_bounds__(128) void ln_kernel(
    const float* __restrict__ x_l, const float* __restrict__ x_r,
    const float* __restrict__ lw_l, const float* __restrict__ lb_l,
    const float* __restrict__ lw_r, const float* __restrict__ lb_r,
    float* __restrict__ out)
{
    __shared__ float red[8];
    int bid = blockIdx.x;
    int stream = bid >> 10;            // NTOK = 1024
    int tok = bid & (NTOK - 1);
    int tid = threadIdx.x;

    const float* p0 = g_part[0 * 2 + stream][tok];
    const float* p1 = g_part[1 * 2 + stream][tok];
    const float* xr = (stream ? x_r : x_l) + (size_t)tok * TD;
    const float* w  = stream ? lw_r : lw_l;
    const float* b  = stream ? lb_r : lb_l;

    int base = tid * 4;
    float4 a = *reinterpret_cast<const float4*>(p0 + base);
    float4 c = *reinterpret_cast<const float4*>(p1 + base);
    float v0 = a.x + c.x, v1 = a.y + c.y, v2 = a.z + c.z, v3 = a.w + c.w;
    float s1 = v0 + v1 + v2 + v3;
    float s2 = v0 * v0 + v1 * v1 + v2 * v2 + v3 * v3;
    #pragma unroll
    for (int o = 16; o; o >>= 1) {
        s1 += __shfl_xor_sync(0xffffffffu, s1, o);
        s2 += __shfl_xor_sync(0xffffffffu, s2, o);
    }
    int warp = tid >> 5, lane = tid & 31;
    if (lane == 0) { red[warp] = s1; red[4 + warp] = s2; }
    __syncthreads();
    float S1 = red[0] + red[1] + red[2] + red[3];
    float S2 = red[4] + red[5] + red[6] + red[7];
    float mu  = S1 * (1.f / TD);
    float var = S2 * (1.f / TD) - mu * mu;
    float rs  = rsqrtf(fmaxf(var, 0.f) + 1e-5f);

    float4 wv = *reinterpret_cast<const float4*>(w + base);
    float4 bv = *reinterpret_cast<const float4*>(b + base);
    float4 xv = *reinterpret_cast<const float4*>(xr + base);
    float4 o;
    o.x = (v0 - mu) * rs * wv.x + bv.x + xv.x;
    o.y = (v1 - mu) * rs * wv.y + bv.y + xv.y;
    o.z = (v2 - mu) * rs * wv.z + bv.z + xv.z;
    o.w = (v3 - mu) * rs * wv.w + bv.w + xv.w;
    *reinterpret_cast<float4*>(out + (size_t)stream * NTOK * TD + (size_t)tok * TD + base) = o;
}

// ---------------- launch ----------------
extern "C" void kernel_launch(void* const* d_in, const int* in_sizes, int n_in,
                              void* d_out, int out_size)
{
    const float* x_l   = (const float*)d_in[0];
    const float* x_r   = (const float*)d_in[1];
    const float* cent  = (const float*)d_in[2];
    const float* projW = (const float*)d_in[3];
    const float* projb = (const float*)d_in[4];
    const float* eW    = (const float*)d_in[5];
    const float* eB    = (const float*)d_in[6];
    const float* lwl   = (const float*)d_in[7];
    const float* lbl   = (const float*)d_in[8];
    const float* lwr   = (const float*)d_in[9];
    const float* lbr   = (const float*)d_in[10];
    float* out = (float*)d_out;

    zero_cnt_kernel<<<1, NE>>>();
    router_kernel<<<NTOK / TPC, 256>>>(x_l, x_r, cent, projW, projb);
    dim3 g(NE, NT);
    expert_gemm_kernel<<<g, 256>>>(x_l, x_r, eW, eB);
    ln_kernel<<<2 * NTOK, 128>>>(x_l, x_r, lwl, lbl, lwr, lbr, out);
}

// round 6
// speedup vs baseline: 1.1805x; 1.0510x over previous
#include <cuda_runtime.h>

// ---------------- problem constants ----------------
#define BSZ   8
#define NC    128
#define TD    512
#define EDIM  64
#define NE    128
#define NTOK  (BSZ*NC)     // 1024 tokens
#define T2    (2*TD)       // 1024 concat dim

// ---------------- GEMM tiling ----------------
#define BN 128             // n-columns per CTA
#define NT (TD/BN)         // 4 n-tiles
#define KC 64              // k-tile
#define MC 32              // m rows per work item
#define NKT (TD/KC)        // 8 k-tiles
#define XP 36              // x smem row pitch (floats)
#define MAXW 256           // max work items (bound: 128 + 2048/32 = 192)

// ---------------- device scratch (no allocation allowed) ----------------
__device__ int   g_cnt[NE];
__device__ int   g_list[NE][NTOK];          // packed token*2 + slot
__device__ int   g_work[MAXW];              // expert | (m-slice << 16)
__device__ int   g_nwork;
__device__ float g_part[4][NTOK][TD];       // [slot*2+stream][token][t]  (8 MB)

// ---------------- f32x2 packed-FMA helpers ----------------
__device__ __forceinline__ unsigned long long fma2(unsigned long long a,
                                                   unsigned long long b,
                                                   unsigned long long c) {
    unsigned long long d;
    asm("fma.rn.f32x2 %0, %1, %2, %3;" : "=l"(d) : "l"(a), "l"(b), "l"(c));
    return d;
}
__device__ __forceinline__ unsigned long long pack2(float lo, float hi) {
    unsigned long long d;
    asm("mov.b64 %0, {%1, %2};" : "=l"(d) : "f"(lo), "f"(hi));
    return d;
}
__device__ __forceinline__ float2 unpack2(unsigned long long v) {
    float2 r;
    asm("mov.b64 {%0, %1}, %2;" : "=f"(r.x), "=f"(r.y) : "l"(v));
    return r;
}

// ---------------- kernel 0: zero per-expert counters ----------------
__global__ void zero_cnt_kernel() { g_cnt[threadIdx.x] = 0; }

// ---------------- kernel 1: router, 4 tokens per CTA ----------------
// s_e = (x @ projW^T + projb) . centers[e]/||centers[e]||
// x_proj L2-norm is a positive per-token scalar (order-preserving) and the
// reference's token-level mask makes each selected expert's combine weight
// exactly softmax(p0)+softmax(p1) = 1.0, so only top-2 indices matter.
#define TPC 4
__global__ __launch_bounds__(256) void router_kernel(
    const float* __restrict__ x_l, const float* __restrict__ x_r,
    const float* __restrict__ centers,
    const float* __restrict__ projW, const float* __restrict__ projb)
{
    __shared__ float xs[TPC][T2];     // 16 KB
    __shared__ float ps[TPC][EDIM];   // 1 KB
    __shared__ float ss[TPC][NE];     // 2 KB
    int tok0 = blockIdx.x * TPC;
    int tid = threadIdx.x;

    #pragma unroll
    for (int t = 0; t < TPC; ++t) {
        const float* xl = x_l + (size_t)(tok0 + t) * TD;
        const float* xr = x_r + (size_t)(tok0 + t) * TD;
        for (int i = tid; i < TD; i += 256) { xs[t][i] = xl[i]; xs[t][i + TD] = xr[i]; }
    }
    __syncthreads();

    int warp = tid >> 5, lane = tid & 31;
    int t_w = warp >> 1;               // token handled by this warp (2 warps/token)
    int jbase = (warp & 1) * 32;       // j half
    for (int it = 0; it < 32; ++it) {
        int j = jbase + it;
        const float* w = projW + (size_t)j * T2;
        float s = 0.f;
        #pragma unroll 4
        for (int k = lane; k < T2; k += 32) s += xs[t_w][k] * w[k];
        #pragma unroll
        for (int o = 16; o; o >>= 1) s += __shfl_xor_sync(0xffffffffu, s, o);
        if (lane == 0) ps[t_w][j] = s + projb[j];
    }
    __syncthreads();

    // 512 (token, expert) scores over 256 threads, 2 rounds
    #pragma unroll
    for (int r = 0; r < 2; ++r) {
        int idx = tid + 256 * r;
        int t = idx >> 7, e = idx & 127;
        const float* c = centers + (size_t)e * EDIM;
        float s = 0.f, n = 0.f;
        #pragma unroll 8
        for (int j = 0; j < EDIM; ++j) { float cv = c[j]; s += ps[t][j] * cv; n += cv * cv; }
        ss[t][e] = s * rsqrtf(fmaxf(n, 1e-24f));
    }
    __syncthreads();

    if (tid < TPC) {
        int t = tid, tok = tok0 + t;
        // strict > keeps first-index tie-break, matching jax.lax.top_k
        int e0 = 0; float b0 = ss[t][0];
        for (int e = 1; e < NE; ++e) if (ss[t][e] > b0) { b0 = ss[t][e]; e0 = e; }
        int e1 = (e0 == 0) ? 1 : 0; float b1 = ss[t][e1];
        for (int e = 0; e < NE; ++e) if (e != e0 && ss[t][e] > b1) { b1 = ss[t][e]; e1 = e; }
        int p0 = atomicAdd(&g_cnt[e0], 1);
        g_list[e0][p0] = tok * 2 + 0;
        int p1 = atomicAdd(&g_cnt[e1], 1);
        g_list[e1][p1] = tok * 2 + 1;
    }
}

// ---------------- kernel 1.5: build balanced work queue ----------------
// one item per (expert, 32-row m-slice); hot experts fan out to many CTAs.
__global__ void scan_kernel() {
    __shared__ int ws[4];
    int e = threadIdx.x;               // 128 threads
    int c = (2 * g_cnt[e] + MC - 1) / MC;
    int lane = e & 31, w = e >> 5;
    int v = c;
    #pragma unroll
    for (int o = 1; o < 32; o <<= 1) {
        int t = __shfl_up_sync(0xffffffffu, v, o);
        if (lane >= o) v += t;
    }
    if (lane == 31) ws[w] = v;
    __syncthreads();
    int add = 0;
    for (int i = 0; i < w; ++i) add += ws[i];
    int excl = add + v - c;
    for (int i = 0; i < c; ++i)
        g_work[excl + i] = e | (i << 16);
    if (e == NE - 1) g_nwork = excl + c;
}

// ---------------- kernel 2: grouped per-expert GEMM (balanced) ----------
// CTA (wi, nt): work item wi = (expert e, m-slice ms); one 32-row pass.
// Inner loop identical to R5 (coalesced W LDG, XOR-swizzled [k][n] smem).
__global__ __launch_bounds__(256) void expert_gemm_kernel(
    const float* __restrict__ x_l, const float* __restrict__ x_r,
    const float* __restrict__ eW,  const float* __restrict__ eB)
{
    __shared__ float Wst[KC * BN];     // 32 KB, phys = k*128 + 4*(quad^(k&31)) + sub
    __shared__ float xst[KC * XP];     // 9 KB,  x[k][m] at k*XP + m

    int wi = blockIdx.x;
    if (wi >= g_nwork) return;
    int item = g_work[wi];
    int e  = item & 0xffff;
    int mp = (item >> 16) * MC;
    int nt = blockIdx.y;
    int cnt = g_cnt[e];
    int rows = 2 * cnt;

    int tid  = threadIdx.x;
    int lane = tid & 31;
    int warp = tid >> 5;
    int m0   = warp * 4;               // warp-uniform m quad
    int N0   = nt * BN;
    const float* We = eW + (size_t)e * TD * TD + (size_t)N0 * TD;
    float4 bias = *reinterpret_cast<const float4*>(eB + (size_t)e * TD + N0 + lane * 4);

    // W loader: 16 lanes along k of one row (coalesced), 8 rows per thread
    int wk4 = (tid & 15) * 4;          // 0..60
    int wn  = tid >> 4;                // 0..15 (+16*i)
    // x loader: 8 lanes along k of one gathered row
    int xk8 = (tid & 7) * 8;           // 0..56
    int xm  = tid >> 3;                // 0..31

    // per-warp m metadata (broadcast loads)
    int tokm[4], strm[4], slotm[4], valm[4];
    #pragma unroll
    for (int i = 0; i < 4; ++i) {
        int r = mp + m0 + i;
        valm[i] = (r < rows);
        int rr = valm[i] ? r : 0;
        int entry = (rr < cnt) ? rr : rr - cnt;
        strm[i] = (rr < cnt) ? 0 : 1;
        int packed = g_list[e][entry];
        tokm[i]  = packed >> 1;
        slotm[i] = packed & 1;
    }
    // x loader row pointer
    const float* xsrc = nullptr;
    {
        int lr = mp + xm;
        if (lr < rows) {
            int entry = (lr < cnt) ? lr : lr - cnt;
            const float* base = (lr < cnt) ? x_l : x_r;
            xsrc = base + (size_t)(g_list[e][entry] >> 1) * TD;
        }
    }

    unsigned long long acc[2][4];  // [n-pair][m]
    #pragma unroll
    for (int p = 0; p < 2; ++p)
        #pragma unroll
        for (int m = 0; m < 4; ++m) acc[p][m] = 0ull;

    for (int kt = 0; kt < NKT; ++kt) {
        int k0 = kt * KC;
        __syncthreads();
        // ---- W tile: 8 coalesced float4 LDG -> swizzled transposed STS ----
        #pragma unroll
        for (int i = 0; i < 8; ++i) {
            int n = wn + 16 * i;
            float4 v = *reinterpret_cast<const float4*>(We + (size_t)n * TD + k0 + wk4);
            int q = n >> 2, sub = n & 3;
            float va[4] = {v.x, v.y, v.z, v.w};
            #pragma unroll
            for (int j = 0; j < 4; ++j) {
                int kk = wk4 + j;
                Wst[kk * BN + ((q ^ (kk & 31)) << 2) + sub] = va[j];
            }
        }
        // ---- x tile: 2 float4 LDG -> transposed STS ----
        #pragma unroll
        for (int i = 0; i < 2; ++i) {
            float4 v = xsrc ? *reinterpret_cast<const float4*>(xsrc + k0 + xk8 + i * 4)
                            : make_float4(0.f, 0.f, 0.f, 0.f);
            int kk = xk8 + i * 4;
            xst[(kk + 0) * XP + xm] = v.x;
            xst[(kk + 1) * XP + xm] = v.y;
            xst[(kk + 2) * XP + xm] = v.z;
            xst[(kk + 3) * XP + xm] = v.w;
        }
        __syncthreads();
        // ---- compute: per k: 1 swizzled W LDS.128 + 1 bcast x LDS.128 ----
        #pragma unroll
        for (int k = 0; k < KC; ++k) {
            ulonglong2 w = *reinterpret_cast<const ulonglong2*>(
                &Wst[k * BN + (((lane ^ (k & 31)) & 31) << 2)]);
            float4 xv = *reinterpret_cast<const float4*>(&xst[k * XP + m0]);
            unsigned long long xd0 = pack2(xv.x, xv.x);
            unsigned long long xd1 = pack2(xv.y, xv.y);
            unsigned long long xd2 = pack2(xv.z, xv.z);
            unsigned long long xd3 = pack2(xv.w, xv.w);
            acc[0][0] = fma2(w.x, xd0, acc[0][0]);
            acc[1][0] = fma2(w.y, xd0, acc[1][0]);
            acc[0][1] = fma2(w.x, xd1, acc[0][1]);
            acc[1][1] = fma2(w.y, xd1, acc[1][1]);
            acc[0][2] = fma2(w.x, xd2, acc[0][2]);
            acc[1][2] = fma2(w.y, xd2, acc[1][2]);
            acc[0][3] = fma2(w.x, xd3, acc[0][3]);
            acc[1][3] = fma2(w.y, xd3, acc[1][3]);
        }
    }

    // ---- epilogue: one float4 STG per valid m row (unique dest) ----
    #pragma unroll
    for (int i = 0; i < 4; ++i) {
        float2 lo = unpack2(acc[0][i]);   // (n0, n1)
        float2 hi = unpack2(acc[1][i]);   // (n2, n3)
        float4 o;
        o.x = lo.x + bias.x;
        o.y = lo.y + bias.y;
        o.z = hi.x + bias.z;
        o.w = hi.y + bias.w;
        float* dst = &g_part[slotm[i] * 2 + strm[i]][tokm[i]][N0 + lane * 4];
        if (valm[i]) *reinterpret_cast<float4*>(dst) = o;
    }
}

// ---------------- kernel 3: combine slots + LayerNorm + residual --------
__global__ __launch_bounds__(128) void ln_kernel(
    const float* __restrict__ x_l, const float* __restrict__ x_r,
    const float* __restrict__ lw_l, const float* __restrict__ lb_l,
    const float* __restrict__ lw_r, const float* __restrict__ lb_r,
    float* __restrict__ out)
{
    __shared__ float red[8];
    int bid = blockIdx.x;
    int stream = bid >> 10;            // NTOK = 1024
    int tok = bid & (NTOK - 1);
    int tid = threadIdx.x;

    const float* p0 = g_part[0 * 2 + stream][tok];
    const float* p1 = g_part[1 * 2 + stream][tok];
    const float* xr = (stream ? x_r : x_l) + (size_t)tok * TD;
    const float* w  = stream ? lw_r : lw_l;
    const float* b  = stream ? lb_r : lb_l;

    int base = tid * 4;
    float4 a = *reinterpret_cast<const float4*>(p0 + base);
    float4 c = *reinterpret_cast<const float4*>(p1 + base);
    float v0 = a.x + c.x, v1 = a.y + c.y, v2 = a.z + c.z, v3 = a.w + c.w;
    float s1 = v0 + v1 + v2 + v3;
    float s2 = v0 * v0 + v1 * v1 + v2 * v2 + v3 * v3;
    #pragma unroll
    for (int o = 16; o; o >>= 1) {
        s1 += __shfl_xor_sync(0xffffffffu, s1, o);
        s2 += __shfl_xor_sync(0xffffffffu, s2, o);
    }
    int warp = tid >> 5, lane = tid & 31;
    if (lane == 0) { red[warp] = s1; red[4 + warp] = s2; }
    __syncthreads();
    float S1 = red[0] + red[1] + red[2] + red[3];
    float S2 = red[4] + red[5] + red[6] + red[7];
    float mu  = S1 * (1.f / TD);
    float var = S2 * (1.f / TD) - mu * mu;
    float rs  = rsqrtf(fmaxf(var, 0.f) + 1e-5f);

    float4 wv = *reinterpret_cast<const float4*>(w + base);
    float4 bv = *reinterpret_cast<const float4*>(b + base);
    float4 xv = *reinterpret_cast<const float4*>(xr + base);
    float4 o;
    o.x = (v0 - mu) * rs * wv.x + bv.x + xv.x;
    o.y = (v1 - mu) * rs * wv.y + bv.y + xv.y;
    o.z = (v2 - mu) * rs * wv.z + bv.z + xv.z;
    o.w = (v3 - mu) * rs * wv.w + bv.w + xv.w;
    *reinterpret_cast<float4*>(out + (size_t)stream * NTOK * TD + (size_t)tok * TD + base) = o;
}

// ---------------- launch ----------------
extern "C" void kernel_launch(void* const* d_in, const int* in_sizes, int n_in,
                              void* d_out, int out_size)
{
    const float* x_l   = (const float*)d_in[0];
    const float* x_r   = (const float*)d_in[1];
    const float* cent  = (const float*)d_in[2];
    const float* projW = (const float*)d_in[3];
    const float* projb = (const float*)d_in[4];
    const float* eW    = (const float*)d_in[5];
    const float* eB    = (const float*)d_in[6];
    const float* lwl   = (const float*)d_in[7];
    const float* lbl   = (const float*)d_in[8];
    const float* lwr   = (const float*)d_in[9];
    const float* lbr   = (const float*)d_in[10];
    float* out = (float*)d_out;

    zero_cnt_kernel<<<1, NE>>>();
    router_kernel<<<NTOK / TPC, 256>>>(x_l, x_r, cent, projW, projb);
    scan_kernel<<<1, NE>>>();
    dim3 g(192, NT);
    expert_gemm_kernel<<<g, 256>>>(x_l, x_r, eW, eB);
    ln_kernel<<<2 * NTOK, 128>>>(x_l, x_r, lwl, lbl, lwr, lbr, out);
}

// round 8
// speedup vs baseline: 2.8630x; 2.4251x over previous
#include <cuda_runtime.h>
#include <cuda_bf16.h>

// ---------------- problem constants ----------------
#define BSZ   8
#define NC    128
#define TD    512
#define EDIM  64
#define NE    128
#define NTOK  (BSZ*NC)     // 1024 tokens
#define T2    (2*TD)       // 1024 concat dim

// ---------------- GEMM tiling ----------------
#define BN 128             // n-columns per CTA
#define NT (TD/BN)         // 4 n-tiles
#define KC 64              // k-tile
#define MC 32              // m rows per work item
#define NKT (TD/KC)        // 8 k-tiles
#define PITCH 36           // smem row pitch in u32 units (32 data + 4 pad)
#define MAXW 256           // max work items

// ---------------- device scratch (no allocation allowed) ----------------
__device__ int   g_cnt[NE];
__device__ int   g_list[NE][NTOK];          // packed token*2 + slot
__device__ int   g_work[MAXW];              // expert | (m-slice << 16)
__device__ int   g_nwork;
__device__ float g_part[4][NTOK][TD];       // [slot*2+stream][token][t]  (8 MB)

// ---------------- helpers ----------------
__device__ __forceinline__ unsigned s2u(const void* p) {
    return (unsigned)__cvta_generic_to_shared(p);
}
__device__ __forceinline__ void ldsm4(unsigned* r, unsigned addr) {
    asm volatile("ldmatrix.sync.aligned.m8n8.x4.shared.b16 {%0,%1,%2,%3},[%4];"
                 : "=r"(r[0]), "=r"(r[1]), "=r"(r[2]), "=r"(r[3]) : "r"(addr));
}
__device__ __forceinline__ void mma16816(float* d, const unsigned* a, const unsigned* b) {
    asm volatile("mma.sync.aligned.m16n8k16.row.col.f32.bf16.bf16.f32 "
                 "{%0,%1,%2,%3},{%4,%5,%6,%7},{%8,%9},{%0,%1,%2,%3};"
                 : "+f"(d[0]), "+f"(d[1]), "+f"(d[2]), "+f"(d[3])
                 : "r"(a[0]), "r"(a[1]), "r"(a[2]), "r"(a[3]), "r"(b[0]), "r"(b[1]));
}
// split fp32 pair -> packed bf16x2 hi + lo (2-term expansion)
__device__ __forceinline__ void split2(float v0, float v1, unsigned& h, unsigned& l) {
    __nv_bfloat162 hb;
    hb.x = __float2bfloat16(v0);
    hb.y = __float2bfloat16(v1);
    h = *reinterpret_cast<unsigned*>(&hb);
    float r0 = v0 - __bfloat162float(hb.x);
    float r1 = v1 - __bfloat162float(hb.y);
    __nv_bfloat162 lb;
    lb.x = __float2bfloat16(r0);
    lb.y = __float2bfloat16(r1);
    l = *reinterpret_cast<unsigned*>(&lb);
}

// ---------------- kernel 0: zero per-expert counters ----------------
__global__ void zero_cnt_kernel() { g_cnt[threadIdx.x] = 0; }

// ---------------- kernel 1: router, 8 tokens per CTA, projW tiled --------
// s_e = (x @ projW^T + projb) . centers[e]/||centers[e]||
// x_proj L2-norm is a positive per-token scalar (order-preserving) and the
// reference's token-level mask makes each selected expert's combine weight
// exactly 1.0, so only the top-2 indices matter.
#define TPC 8
__global__ __launch_bounds__(256) void router_kernel(
    const float* __restrict__ x_l, const float* __restrict__ x_r,
    const float* __restrict__ centers,
    const float* __restrict__ projW, const float* __restrict__ projb)
{
    __shared__ float xs[TPC][T2];   // 32 KB
    __shared__ float wt[2][T2];     // 8 KB
    __shared__ float ps[TPC][EDIM]; // 2 KB
    __shared__ float ss[TPC][NE];   // 4 KB
    int tok0 = blockIdx.x * TPC;
    int tid = threadIdx.x;
    int warp = tid >> 5, lane = tid & 31;

    // load 8 token rows (both streams) vectorized
    {
        int h = tid >> 7, i = tid & 127;   // 128 float4 per stream-row
        #pragma unroll
        for (int t = 0; t < TPC; ++t) {
            const float* src = (h ? x_r : x_l) + (size_t)(tok0 + t) * TD;
            reinterpret_cast<float4*>(&xs[t][h * TD])[i] =
                reinterpret_cast<const float4*>(src)[i];
        }
    }

    for (int jc = 0; jc < 32; ++jc) {
        __syncthreads();
        // stage 2 projW rows (8 KB) cooperatively
        const float4* src = reinterpret_cast<const float4*>(projW + (size_t)(jc * 2) * T2);
        reinterpret_cast<float4*>(wt)[tid]       = src[tid];
        reinterpret_cast<float4*>(wt)[tid + 256] = src[tid + 256];
        __syncthreads();
        int t = warp;   // warp <-> token
        #pragma unroll
        for (int jj = 0; jj < 2; ++jj) {
            float s = 0.f;
            #pragma unroll
            for (int kk = 0; kk < 8; ++kk) {
                int k = (kk * 32 + lane) * 4;
                float4 a = *reinterpret_cast<const float4*>(&xs[t][k]);
                float4 b = *reinterpret_cast<const float4*>(&wt[jj][k]);
                s += a.x * b.x + a.y * b.y + a.z * b.z + a.w * b.w;
            }
            #pragma unroll
            for (int o = 16; o; o >>= 1) s += __shfl_xor_sync(0xffffffffu, s, o);
            if (lane == 0) ps[t][jc * 2 + jj] = s + projb[jc * 2 + jj];
        }
    }
    __syncthreads();

    // 1024 (token, expert) scores over 256 threads, 4 rounds
    #pragma unroll
    for (int r = 0; r < 4; ++r) {
        int idx = tid + 256 * r;
        int t = idx >> 7, e = idx & 127;
        const float* c = centers + (size_t)e * EDIM;
        float s = 0.f, n = 0.f;
        #pragma unroll 8
        for (int j = 0; j < EDIM; ++j) { float cv = c[j]; s += ps[t][j] * cv; n += cv * cv; }
        ss[t][e] = s * rsqrtf(fmaxf(n, 1e-24f));
    }
    __syncthreads();

    if (tid < TPC) {
        int t = tid, tok = tok0 + t;
        // strict > keeps first-index tie-break, matching jax.lax.top_k
        int e0 = 0; float b0 = ss[t][0];
        for (int e = 1; e < NE; ++e) if (ss[t][e] > b0) { b0 = ss[t][e]; e0 = e; }
        int e1 = (e0 == 0) ? 1 : 0; float b1 = ss[t][e1];
        for (int e = 0; e < NE; ++e) if (e != e0 && ss[t][e] > b1) { b1 = ss[t][e]; e1 = e; }
        int p0 = atomicAdd(&g_cnt[e0], 1);
        g_list[e0][p0] = tok * 2 + 0;
        int p1 = atomicAdd(&g_cnt[e1], 1);
        g_list[e1][p1] = tok * 2 + 1;
    }
}

// ---------------- kernel 1.5: build balanced work queue ----------------
__global__ void scan_kernel() {
    __shared__ int ws[4];
    int e = threadIdx.x;               // 128 threads
    int c = (2 * g_cnt[e] + MC - 1) / MC;
    int lane = e & 31, w = e >> 5;
    int v = c;
    #pragma unroll
    for (int o = 1; o < 32; o <<= 1) {
        int t = __shfl_up_sync(0xffffffffu, v, o);
        if (lane >= o) v += t;
    }
    if (lane == 31) ws[w] = v;
    __syncthreads();
    int add = 0;
    for (int i = 0; i < w; ++i) add += ws[i];
    int excl = add + v - c;
    for (int i = 0; i < c; ++i)
        g_work[excl + i] = e | (i << 16);
    if (e == NE - 1) g_nwork = excl + c;
}

// ---------------- kernel 2: grouped GEMM via bf16-split HMMA ------------
// CTA (wi, nt): 32 gathered rows x 128 n-cols x K=512.
// W and x split into bf16 hi+lo planes in smem; products hh + hl + lh give
// ~fp32 accuracy. Frags fed by ldmatrix (conflict-free, PITCH = 36 u32).
__global__ __launch_bounds__(256) void expert_gemm_kernel(
    const float* __restrict__ x_l, const float* __restrict__ x_r,
    const float* __restrict__ eW,  const float* __restrict__ eB)
{
    __shared__ unsigned Whi[BN * PITCH];   // 18.4 KB each
    __shared__ unsigned Wlo[BN * PITCH];
    __shared__ unsigned Xhi[MC * PITCH];   // 4.6 KB each
    __shared__ unsigned Xlo[MC * PITCH];

    int wi = blockIdx.x;
    if (wi >= g_nwork) return;
    int item = g_work[wi];
    int e  = item & 0xffff;
    int mp = (item >> 16) * MC;
    int nt = blockIdx.y;
    int cnt = g_cnt[e];
    int rows = 2 * cnt;

    int tid = threadIdx.x, lane = tid & 31, warp = tid >> 5;
    int mhalf = (warp & 1) * 16;       // warp's 16-row half
    int ng    = (warp >> 1) * 32;      // warp's 32-col group
    int N0    = nt * BN;
    const float* We = eW + (size_t)e * TD * TD + (size_t)N0 * TD;

    int g  = lane >> 2;                // accum row group 0..7
    int t2 = (lane & 3) * 2;           // accum col pair

    // bias (per n-tile float2)
    float2 bv[4];
    #pragma unroll
    for (int q = 0; q < 4; ++q)
        bv[q] = *reinterpret_cast<const float2*>(eB + (size_t)e * TD + N0 + ng + q * 8 + t2);

    // row metadata for this thread's 2 output rows
    int tokr[2], dsel[2], valr[2];
    #pragma unroll
    for (int i = 0; i < 2; ++i) {
        int r = mp + mhalf + g + i * 8;
        valr[i] = (r < rows);
        int rr = valr[i] ? r : 0;
        int entry = (rr < cnt) ? rr : rr - cnt;
        int str = (rr < cnt) ? 0 : 1;
        int packed = g_list[e][entry];
        tokr[i] = packed >> 1;
        dsel[i] = (packed & 1) * 2 + str;
    }

    // x loader (row xm of slice, 8 k per thread)
    int xm = tid >> 3, xk8 = (tid & 7) * 8;
    const float* xsrc = nullptr;
    {
        int lr = mp + xm;
        if (lr < rows) {
            int entry = (lr < cnt) ? lr : lr - cnt;
            const float* base = (lr < cnt) ? x_l : x_r;
            xsrc = base + (size_t)(g_list[e][entry] >> 1) * TD;
        }
    }
    // W loader (rows wn+16i, 4 k per float4)
    int wn = tid >> 4, wk4 = (tid & 15) * 4;

    float acc[4][4];
    #pragma unroll
    for (int q = 0; q < 4; ++q)
        #pragma unroll
        for (int i = 0; i < 4; ++i) acc[q][i] = 0.f;

    // ldmatrix lane offsets (u32 units)
    unsigned aOffU  = (unsigned)((mhalf + (lane & 15)) * PITCH + ((lane >> 4) & 1) * 4);
    unsigned brow   = (unsigned)(ng + ((lane >> 4) & 1) * 8 + (lane & 7));
    unsigned bkU    = (unsigned)(((lane >> 3) & 1) * 4);
    unsigned bOffU0 = brow * PITCH + bkU;
    unsigned bOffU1 = (brow + 16) * PITCH + bkU;

    unsigned XhiA = s2u(Xhi), XloA = s2u(Xlo), WhiA = s2u(Whi), WloA = s2u(Wlo);

    for (int kt = 0; kt < NKT; ++kt) {
        int k0 = kt * KC;
        __syncthreads();
        // ---- stage W tile as bf16 hi/lo planes ----
        #pragma unroll
        for (int i = 0; i < 8; ++i) {
            int n = wn + 16 * i;
            float4 v = *reinterpret_cast<const float4*>(We + (size_t)n * TD + k0 + wk4);
            unsigned h0, l0, h1, l1;
            split2(v.x, v.y, h0, l0);
            split2(v.z, v.w, h1, l1);
            int u = n * PITCH + (wk4 >> 1);
            *reinterpret_cast<uint2*>(&Whi[u]) = make_uint2(h0, h1);
            *reinterpret_cast<uint2*>(&Wlo[u]) = make_uint2(l0, l1);
        }
        // ---- stage x tile ----
        #pragma unroll
        for (int i = 0; i < 2; ++i) {
            float4 v = xsrc ? *reinterpret_cast<const float4*>(xsrc + k0 + xk8 + i * 4)
                            : make_float4(0.f, 0.f, 0.f, 0.f);
            unsigned h0, l0, h1, l1;
            split2(v.x, v.y, h0, l0);
            split2(v.z, v.w, h1, l1);
            int u = xm * PITCH + ((xk8 + i * 4) >> 1);
            *reinterpret_cast<uint2*>(&Xhi[u]) = make_uint2(h0, h1);
            *reinterpret_cast<uint2*>(&Xlo[u]) = make_uint2(l0, l1);
        }
        __syncthreads();
        // ---- 4 k16-chunks: ldmatrix + 12 HMMA each ----
        #pragma unroll
        for (int c = 0; c < 4; ++c) {
            unsigned cu4 = (unsigned)(c * 8) * 4u;   // byte offset of chunk
            unsigned ahi[4], alo[4], b0h[4], b1h[4], b0l[4], b1l[4];
            ldsm4(ahi, XhiA + (aOffU * 4u) + cu4);
            ldsm4(alo, XloA + (aOffU * 4u) + cu4);
            ldsm4(b0h, WhiA + (bOffU0 * 4u) + cu4);
            ldsm4(b1h, WhiA + (bOffU1 * 4u) + cu4);
            ldsm4(b0l, WloA + (bOffU0 * 4u) + cu4);
            ldsm4(b1l, WloA + (bOffU1 * 4u) + cu4);
            // n-tiles 0..3: (b0h[0:2], b0h[2:4], b1h[0:2], b1h[2:4])
            mma16816(acc[0], ahi, b0h + 0);
            mma16816(acc[1], ahi, b0h + 2);
            mma16816(acc[2], ahi, b1h + 0);
            mma16816(acc[3], ahi, b1h + 2);
            mma16816(acc[0], ahi, b0l + 0);
            mma16816(acc[1], ahi, b0l + 2);
            mma16816(acc[2], ahi, b1l + 0);
            mma16816(acc[3], ahi, b1l + 2);
            mma16816(acc[0], alo, b0h + 0);
            mma16816(acc[1], alo, b0h + 2);
            mma16816(acc[2], alo, b1h + 0);
            mma16816(acc[3], alo, b1h + 2);
        }
    }

    // ---- epilogue: float2 STG per (row, n-tile) ----
    #pragma unroll
    for (int q = 0; q < 4; ++q) {
        int n = N0 + ng + q * 8 + t2;
        if (valr[0]) {
            float2 o = make_float2(acc[q][0] + bv[q].x, acc[q][1] + bv[q].y);
            *reinterpret_cast<float2*>(&g_part[dsel[0]][tokr[0]][n]) = o;
        }
        if (valr[1]) {
            float2 o = make_float2(acc[q][2] + bv[q].x, acc[q][3] + bv[q].y);
            *reinterpret_cast<float2*>(&g_part[dsel[1]][tokr[1]][n]) = o;
        }
    }
}

// ---------------- kernel 3: combine slots + LayerNorm + residual --------
__global__ __launch_bounds__(128) void ln_kernel(
    const float* __restrict__ x_l, const float* __restrict__ x_r,
    const float* __restrict__ lw_l, const float* __restrict__ lb_l,
    const float* __restrict__ lw_r, const float* __restrict__ lb_r,
    float* __restrict__ out)
{
    __shared__ float red[8];
    int bid = blockIdx.x;
    int stream = bid >> 10;            // NTOK = 1024
    int tok = bid & (NTOK - 1);
    int tid = threadIdx.x;

    const float* p0 = g_part[0 * 2 + stream][tok];
    const float* p1 = g_part[1 * 2 + stream][tok];
    const float* xr = (stream ? x_r : x_l) + (size_t)tok * TD;
    const float* w  = stream ? lw_r : lw_l;
    const float* b  = stream ? lb_r : lb_l;

    int base = tid * 4;
    float4 a = *reinterpret_cast<const float4*>(p0 + base);
    float4 c = *reinterpret_cast<const float4*>(p1 + base);
    float v0 = a.x + c.x, v1 = a.y + c.y, v2 = a.z + c.z, v3 = a.w + c.w;
    float s1 = v0 + v1 + v2 + v3;
    float s2 = v0 * v0 + v1 * v1 + v2 * v2 + v3 * v3;
    #pragma unroll
    for (int o = 16; o; o >>= 1) {
        s1 += __shfl_xor_sync(0xffffffffu, s1, o);
        s2 += __shfl_xor_sync(0xffffffffu, s2, o);
    }
    int warp = tid >> 5, lane = tid & 31;
    if (lane == 0) { red[warp] = s1; red[4 + warp] = s2; }
    __syncthreads();
    float S1 = red[0] + red[1] + red[2] + red[3];
    float S2 = red[4] + red[5] + red[6] + red[7];
    float mu  = S1 * (1.f / TD);
    float var = S2 * (1.f / TD) - mu * mu;
    float rs  = rsqrtf(fmaxf(var, 0.f) + 1e-5f);

    float4 wv = *reinterpret_cast<const float4*>(w + base);
    float4 bv = *reinterpret_cast<const float4*>(b + base);
    float4 xv = *reinterpret_cast<const float4*>(xr + base);
    float4 o;
    o.x = (v0 - mu) * rs * wv.x + bv.x + xv.x;
    o.y = (v1 - mu) * rs * wv.y + bv.y + xv.y;
    o.z = (v2 - mu) * rs * wv.z + bv.z + xv.z;
    o.w = (v3 - mu) * rs * wv.w + bv.w + xv.w;
    *reinterpret_cast<float4*>(out + (size_t)stream * NTOK * TD + (size_t)tok * TD + base) = o;
}

// ---------------- launch ----------------
extern "C" void kernel_launch(void* const* d_in, const int* in_sizes, int n_in,
                              void* d_out, int out_size)
{
    const float* x_l   = (const float*)d_in[0];
    const float* x_r   = (const float*)d_in[1];
    const float* cent  = (const float*)d_in[2];
    const float* projW = (const float*)d_in[3];
    const float* projb = (const float*)d_in[4];
    const float* eW    = (const float*)d_in[5];
    const float* eB    = (const float*)d_in[6];
    const float* lwl   = (const float*)d_in[7];
    const float* lbl   = (const float*)d_in[8];
    const float* lwr   = (const float*)d_in[9];
    const float* lbr   = (const float*)d_in[10];
    float* out = (float*)d_out;

    zero_cnt_kernel<<<1, NE>>>();
    router_kernel<<<NTOK / TPC, 256>>>(x_l, x_r, cent, projW, projb);
    scan_kernel<<<1, NE>>>();
    dim3 g(192, NT);
    expert_gemm_kernel<<<g, 256>>>(x_l, x_r, eW, eB);
    ln_kernel<<<2 * NTOK, 128>>>(x_l, x_r, lwl, lbl, lwr, lbr, out);
}

// round 11
// speedup vs baseline: 2.8831x; 1.0070x over previous
#include <cuda_runtime.h>
#include <cuda_bf16.h>

// ---------------- problem constants ----------------
#define BSZ   8
#define NC    128
#define TD    512
#define EDIM  64
#define NE    128
#define NTOK  (BSZ*NC)     // 1024 tokens
#define T2    (2*TD)       // 1024 concat dim

// ---------------- GEMM tiling ----------------
#define BN 128             // n-columns per CTA
#define NT (TD/BN)         // 4 n-tiles
#define KC 64              // k-tile
#define MC 32              // m rows per work item
#define NKT (TD/KC)        // 8 k-tiles
#define PITCH 36           // smem row pitch in u32 units (32 data + 4 pad)
#define MAXW 256           // max work items

// ---------------- device scratch (no allocation allowed) ----------------
__device__ int   g_cnt[NE];
__device__ int   g_list[NE][NTOK];          // packed token*2 + slot
__device__ int   g_work[MAXW];              // expert | (m-slice << 16)
__device__ int   g_nwork;
__device__ float g_part[4][NTOK][TD];       // [slot*2+stream][token][t]  (8 MB)

// ---------------- helpers ----------------
__device__ __forceinline__ unsigned s2u(const void* p) {
    return (unsigned)__cvta_generic_to_shared(p);
}
__device__ __forceinline__ void ldsm4(unsigned* r, unsigned addr) {
    asm volatile("ldmatrix.sync.aligned.m8n8.x4.shared.b16 {%0,%1,%2,%3},[%4];"
                 : "=r"(r[0]), "=r"(r[1]), "=r"(r[2]), "=r"(r[3]) : "r"(addr));
}
__device__ __forceinline__ void mma16816(float* d, const unsigned* a, const unsigned* b) {
    asm volatile("mma.sync.aligned.m16n8k16.row.col.f32.bf16.bf16.f32 "
                 "{%0,%1,%2,%3},{%4,%5,%6,%7},{%8,%9},{%0,%1,%2,%3};"
                 : "+f"(d[0]), "+f"(d[1]), "+f"(d[2]), "+f"(d[3])
                 : "r"(a[0]), "r"(a[1]), "r"(a[2]), "r"(a[3]), "r"(b[0]), "r"(b[1]));
}
// split fp32 pair -> packed bf16x2 hi + lo (2-term expansion)
__device__ __forceinline__ void split2(float v0, float v1, unsigned& h, unsigned& l) {
    __nv_bfloat162 hb;
    hb.x = __float2bfloat16(v0);
    hb.y = __float2bfloat16(v1);
    h = *reinterpret_cast<unsigned*>(&hb);
    float r0 = v0 - __bfloat162float(hb.x);
    float r1 = v1 - __bfloat162float(hb.y);
    __nv_bfloat162 lb;
    lb.x = __float2bfloat16(r0);
    lb.y = __float2bfloat16(r1);
    l = *reinterpret_cast<unsigned*>(&lb);
}

// ---------------- kernel 0: zero per-expert counters ----------------
__global__ void zero_cnt_kernel() { g_cnt[threadIdx.x] = 0; }

// ---------------- kernel 1: router, 8 tokens/CTA, pipelined projW --------
// s_e = (x @ projW^T + projb) . centers[e]/||centers[e]||
// x_proj L2-norm is a positive per-token scalar (order-preserving) and the
// reference's token-level mask makes each selected expert's combine weight
// exactly 1.0, so only the top-2 indices matter.
#define TPC 8
__global__ __launch_bounds__(256) void router_kernel(
    const float* __restrict__ x_l, const float* __restrict__ x_r,
    const float* __restrict__ centers,
    const float* __restrict__ projW, const float* __restrict__ projb)
{
    __shared__ float xs[TPC][T2];      // 32 KB
    __shared__ float wt[2][2][T2];     // 16 KB ping-pong (2 rows per chunk)
    __shared__ float ps[TPC][EDIM];    // 2 KB
    __shared__ float ss[TPC][NE];      // 4 KB
    int tok0 = blockIdx.x * TPC;
    int tid = threadIdx.x;
    int warp = tid >> 5, lane = tid & 31;

    // load 8 token rows (both streams) vectorized
    {
        int h = tid >> 7, i = tid & 127;   // 128 float4 per stream-row
        #pragma unroll
        for (int t = 0; t < TPC; ++t) {
            const float* src = (h ? x_r : x_l) + (size_t)(tok0 + t) * TD;
            reinterpret_cast<float4*>(&xs[t][h * TD])[i] =
                reinterpret_cast<const float4*>(src)[i];
        }
    }

    // prologue: stage chunk 0
    {
        const float4* src = reinterpret_cast<const float4*>(projW);
        float4 a = src[tid], b = src[tid + 256];
        reinterpret_cast<float4*>(wt[0])[tid]       = a;
        reinterpret_cast<float4*>(wt[0])[tid + 256] = b;
    }
    __syncthreads();

    for (int jc = 0; jc < 32; ++jc) {
        int p = jc & 1;
        // prefetch next chunk into regs (overlaps with compute)
        float4 nxa, nxb;
        if (jc + 1 < 32) {
            const float4* src = reinterpret_cast<const float4*>(projW + (size_t)((jc + 1) * 2) * T2);
            nxa = src[tid];
            nxb = src[tid + 256];
        }
        int t = warp;   // warp <-> token
        #pragma unroll
        for (int jj = 0; jj < 2; ++jj) {
            float s = 0.f;
            #pragma unroll
            for (int kk = 0; kk < 8; ++kk) {
                int k = (kk * 32 + lane) * 4;
                float4 a = *reinterpret_cast<const float4*>(&xs[t][k]);
                float4 b = *reinterpret_cast<const float4*>(&wt[p][jj][k]);
                s += a.x * b.x + a.y * b.y + a.z * b.z + a.w * b.w;
            }
            #pragma unroll
            for (int o = 16; o; o >>= 1) s += __shfl_xor_sync(0xffffffffu, s, o);
            if (lane == 0) ps[t][jc * 2 + jj] = s + projb[jc * 2 + jj];
        }
        if (jc + 1 < 32) {
            reinterpret_cast<float4*>(wt[p ^ 1])[tid]       = nxa;
            reinterpret_cast<float4*>(wt[p ^ 1])[tid + 256] = nxb;
        }
        __syncthreads();
    }

    // 1024 (token, expert) scores over 256 threads, 4 rounds
    #pragma unroll
    for (int r = 0; r < 4; ++r) {
        int idx = tid + 256 * r;
        int t = idx >> 7, e = idx & 127;
        const float* c = centers + (size_t)e * EDIM;
        float s = 0.f, n = 0.f;
        #pragma unroll 8
        for (int j = 0; j < EDIM; ++j) { float cv = c[j]; s += ps[t][j] * cv; n += cv * cv; }
        ss[t][e] = s * rsqrtf(fmaxf(n, 1e-24f));
    }
    __syncthreads();

    // warp-parallel top-2: warp t reduces token t's 128 scores.
    // tie-break: smaller index wins (matches jax.lax.top_k first-index).
    {
        int t = warp;
        float v[4]; int id[4];
        #pragma unroll
        for (int q = 0; q < 4; ++q) { id[q] = lane + 32 * q; v[q] = ss[t][id[q]]; }
        // local argmax over 4
        float bv_ = v[0]; int bi = id[0];
        #pragma unroll
        for (int q = 1; q < 4; ++q)
            if (v[q] > bv_ || (v[q] == bv_ && id[q] < bi)) { bv_ = v[q]; bi = id[q]; }
        float m1v = bv_; int m1i = bi;
        #pragma unroll
        for (int o = 16; o; o >>= 1) {
            float ov = __shfl_xor_sync(0xffffffffu, m1v, o);
            int   oi = __shfl_xor_sync(0xffffffffu, m1i, o);
            if (ov > m1v || (ov == m1v && oi < m1i)) { m1v = ov; m1i = oi; }
        }
        // second max: invalidate e0, redo local + warp reduce
        bv_ = -3.4e38f; bi = 0x7fffffff;
        #pragma unroll
        for (int q = 0; q < 4; ++q)
            if (id[q] != m1i && (v[q] > bv_ || (v[q] == bv_ && id[q] < bi))) { bv_ = v[q]; bi = id[q]; }
        float m2v = bv_; int m2i = bi;
        #pragma unroll
        for (int o = 16; o; o >>= 1) {
            float ov = __shfl_xor_sync(0xffffffffu, m2v, o);
            int   oi = __shfl_xor_sync(0xffffffffu, m2i, o);
            if (ov > m2v || (ov == m2v && oi < m2i)) { m2v = ov; m2i = oi; }
        }
        if (lane == 0) {
            int tok = tok0 + t;
            int p0 = atomicAdd(&g_cnt[m1i], 1);
            g_list[m1i][p0] = tok * 2 + 0;
            int p1 = atomicAdd(&g_cnt[m2i], 1);
            g_list[m2i][p1] = tok * 2 + 1;
        }
    }
}

// ---------------- kernel 1.5: build balanced work queue ----------------
__global__ void scan_kernel() {
    __shared__ int ws[4];
    int e = threadIdx.x;               // 128 threads
    int c = (2 * g_cnt[e] + MC - 1) / MC;
    int lane = e & 31, w = e >> 5;
    int v = c;
    #pragma unroll
    for (int o = 1; o < 32; o <<= 1) {
        int t = __shfl_up_sync(0xffffffffu, v, o);
        if (lane >= o) v += t;
    }
    if (lane == 31) ws[w] = v;
    __syncthreads();
    int add = 0;
    for (int i = 0; i < w; ++i) add += ws[i];
    int excl = add + v - c;
    for (int i = 0; i < c; ++i)
        g_work[excl + i] = e | (i << 16);
    if (e == NE - 1) g_nwork = excl + c;
}

// ---------------- kernel 2: grouped GEMM via bf16-split HMMA ------------
// CTA (wi, nt): 32 gathered rows x 128 n-cols x K=512.
// W and x split into bf16 hi+lo planes in smem; products hh + hl + lh give
// ~fp32 accuracy. Frags fed by ldmatrix (conflict-free, PITCH = 36 u32).
// launch_bounds(256,4): cap regs at 64 -> 4 CTAs/SM (was reg-limited to 3).
__global__ __launch_bounds__(256, 4) void expert_gemm_kernel(
    const float* __restrict__ x_l, const float* __restrict__ x_r,
    const float* __restrict__ eW,  const float* __restrict__ eB)
{
    __shared__ unsigned Whi[BN * PITCH];   // 18.4 KB each
    __shared__ unsigned Wlo[BN * PITCH];
    __shared__ unsigned Xhi[MC * PITCH];   // 4.6 KB each
    __shared__ unsigned Xlo[MC * PITCH];

    int wi = blockIdx.x;
    if (wi >= g_nwork) return;
    int item = g_work[wi];
    int e  = item & 0xffff;
    int mp = (item >> 16) * MC;
    int nt = blockIdx.y;
    int cnt = g_cnt[e];
    int rows = 2 * cnt;

    int tid = threadIdx.x, lane = tid & 31, warp = tid >> 5;
    int mhalf = (warp & 1) * 16;       // warp's 16-row half
    int ng    = (warp >> 1) * 32;      // warp's 32-col group
    int N0    = nt * BN;
    const float* We = eW + (size_t)e * TD * TD + (size_t)N0 * TD;

    int g  = lane >> 2;                // accum row group 0..7
    int t2 = (lane & 3) * 2;           // accum col pair

    // bias (per n-tile float2)
    float2 bv[4];
    #pragma unroll
    for (int q = 0; q < 4; ++q)
        bv[q] = *reinterpret_cast<const float2*>(eB + (size_t)e * TD + N0 + ng + q * 8 + t2);

    // row metadata for this thread's 2 output rows
    int tokr[2], dsel[2], valr[2];
    #pragma unroll
    for (int i = 0; i < 2; ++i) {
        int r = mp + mhalf + g + i * 8;
        valr[i] = (r < rows);
        int rr = valr[i] ? r : 0;
        int entry = (rr < cnt) ? rr : rr - cnt;
        int str = (rr < cnt) ? 0 : 1;
        int packed = g_list[e][entry];
        tokr[i] = packed >> 1;
        dsel[i] = (packed & 1) * 2 + str;
    }

    // x loader (row xm of slice, 8 k per thread)
    int xm = tid >> 3, xk8 = (tid & 7) * 8;
    const float* xsrc = nullptr;
    {
        int lr = mp + xm;
        if (lr < rows) {
            int entry = (lr < cnt) ? lr : lr - cnt;
            const float* base = (lr < cnt) ? x_l : x_r;
            xsrc = base + (size_t)(g_list[e][entry] >> 1) * TD;
        }
    }
    // W loader (rows wn+16i, 4 k per float4)
    int wn = tid >> 4, wk4 = (tid & 15) * 4;

    float acc[4][4];
    #pragma unroll
    for (int q = 0; q < 4; ++q)
        #pragma unroll
        for (int i = 0; i < 4; ++i) acc[q][i] = 0.f;

    // ldmatrix lane offsets (u32 units)
    unsigned aOffU  = (unsigned)((mhalf + (lane & 15)) * PITCH + ((lane >> 4) & 1) * 4);
    unsigned brow   = (unsigned)(ng + ((lane >> 4) & 1) * 8 + (lane & 7));
    unsigned bkU    = (unsigned)(((lane >> 3) & 1) * 4);
    unsigned bOffU0 = brow * PITCH + bkU;
    unsigned bOffU1 = (brow + 16) * PITCH + bkU;

    unsigned XhiA = s2u(Xhi), XloA = s2u(Xlo), WhiA = s2u(Whi), WloA = s2u(Wlo);

    for (int kt = 0; kt < NKT; ++kt) {
        int k0 = kt * KC;
        __syncthreads();
        // ---- stage W tile as bf16 hi/lo planes ----
        #pragma unroll
        for (int i = 0; i < 8; ++i) {
            int n = wn + 16 * i;
            float4 v = *reinterpret_cast<const float4*>(We + (size_t)n * TD + k0 + wk4);
            unsigned h0, l0, h1, l1;
            split2(v.x, v.y, h0, l0);
            split2(v.z, v.w, h1, l1);
            int u = n * PITCH + (wk4 >> 1);
            *reinterpret_cast<uint2*>(&Whi[u]) = make_uint2(h0, h1);
            *reinterpret_cast<uint2*>(&Wlo[u]) = make_uint2(l0, l1);
        }
        // ---- stage x tile ----
        #pragma unroll
        for (int i = 0; i < 2; ++i) {
            float4 v = xsrc ? *reinterpret_cast<const float4*>(xsrc + k0 + xk8 + i * 4)
                            : make_float4(0.f, 0.f, 0.f, 0.f);
            unsigned h0, l0, h1, l1;
            split2(v.x, v.y, h0, l0);
            split2(v.z, v.w, h1, l1);
            int u = xm * PITCH + ((xk8 + i * 4) >> 1);
            *reinterpret_cast<uint2*>(&Xhi[u]) = make_uint2(h0, h1);
            *reinterpret_cast<uint2*>(&Xlo[u]) = make_uint2(l0, l1);
        }
        __syncthreads();
        // ---- 4 k16-chunks: ldmatrix + 12 HMMA each ----
        #pragma unroll
        for (int c = 0; c < 4; ++c) {
            unsigned cu4 = (unsigned)(c * 8) * 4u;   // byte offset of chunk
            unsigned ahi[4], alo[4], b0h[4], b1h[4], b0l[4], b1l[4];
            ldsm4(ahi, XhiA + (aOffU * 4u) + cu4);
            ldsm4(alo, XloA + (aOffU * 4u) + cu4);
            ldsm4(b0h, WhiA + (bOffU0 * 4u) + cu4);
            ldsm4(b1h, WhiA + (bOffU1 * 4u) + cu4);
            ldsm4(b0l, WloA + (bOffU0 * 4u) + cu4);
            ldsm4(b1l, WloA + (bOffU1 * 4u) + cu4);
            // n-tiles 0..3: (b0h[0:2], b0h[2:4], b1h[0:2], b1h[2:4])
            mma16816(acc[0], ahi, b0h + 0);
            mma16816(acc[1], ahi, b0h + 2);
            mma16816(acc[2], ahi, b1h + 0);
            mma16816(acc[3], ahi, b1h + 2);
            mma16816(acc[0], ahi, b0l + 0);
            mma16816(acc[1], ahi, b0l + 2);
            mma16816(acc[2], ahi, b1l + 0);
            mma16816(acc[3], ahi, b1l + 2);
            mma16816(acc[0], alo, b0h + 0);
            mma16816(acc[1], alo, b0h + 2);
            mma16816(acc[2], alo, b1h + 0);
            mma16816(acc[3], alo, b1h + 2);
        }
    }

    // ---- epilogue: float2 STG per (row, n-tile) ----
    #pragma unroll
    for (int q = 0; q < 4; ++q) {
        int n = N0 + ng + q * 8 + t2;
        if (valr[0]) {
            float2 o = make_float2(acc[q][0] + bv[q].x, acc[q][1] + bv[q].y);
            *reinterpret_cast<float2*>(&g_part[dsel[0]][tokr[0]][n]) = o;
        }
        if (valr[1]) {
            float2 o = make_float2(acc[q][2] + bv[q].x, acc[q][3] + bv[q].y);
            *reinterpret_cast<float2*>(&g_part[dsel[1]][tokr[1]][n]) = o;
        }
    }
}

// ---------------- kernel 3: combine slots + LayerNorm + residual --------
__global__ __launch_bounds__(128) void ln_kernel(
    const float* __restrict__ x_l, const float* __restrict__ x_r,
    const float* __restrict__ lw_l, const float* __restrict__ lb_l,
    const float* __restrict__ lw_r, const float* __restrict__ lb_r,
    float* __restrict__ out)
{
    __shared__ float red[8];
    int bid = blockIdx.x;
    int stream = bid >> 10;            // NTOK = 1024
    int tok = bid & (NTOK - 1);
    int tid = threadIdx.x;

    const float* p0 = g_part[0 * 2 + stream][tok];
    const float* p1 = g_part[1 * 2 + stream][tok];
    const float* xr = (stream ? x_r : x_l) + (size_t)tok * TD;
    const float* w  = stream ? lw_r : lw_l;
    const float* b  = stream ? lb_r : lb_l;

    int base = tid * 4;
    float4 a = *reinterpret_cast<const float4*>(p0 + base);
    float4 c = *reinterpret_cast<const float4*>(p1 + base);
    float v0 = a.x + c.x, v1 = a.y + c.y, v2 = a.z + c.z, v3 = a.w + c.w;
    float s1 = v0 + v1 + v2 + v3;
    float s2 = v0 * v0 + v1 * v1 + v2 * v2 + v3 * v3;
    #pragma unroll
    for (int o = 16; o; o >>= 1) {
        s1 += __shfl_xor_sync(0xffffffffu, s1, o);
        s2 += __shfl_xor_sync(0xffffffffu, s2, o);
    }
    int warp = tid >> 5, lane = tid & 31;
    if (lane == 0) { red[warp] = s1; red[4 + warp] = s2; }
    __syncthreads();
    float S1 = red[0] + red[1] + red[2] + red[3];
    float S2 = red[4] + red[5] + red[6] + red[7];
    float mu  = S1 * (1.f / TD);
    float var = S2 * (1.f / TD) - mu * mu;
    float rs  = rsqrtf(fmaxf(var, 0.f) + 1e-5f);

    float4 wv = *reinterpret_cast<const float4*>(w + base);
    float4 bv = *reinterpret_cast<const float4*>(b + base);
    float4 xv = *reinterpret_cast<const float4*>(xr + base);
    float4 o;
    o.x = (v0 - mu) * rs * wv.x + bv.x + xv.x;
    o.y = (v1 - mu) * rs * wv.y + bv.y + xv.y;
    o.z = (v2 - mu) * rs * wv.z + bv.z + xv.z;
    o.w = (v3 - mu) * rs * wv.w + bv.w + xv.w;
    *reinterpret_cast<float4*>(out + (size_t)stream * NTOK * TD + (size_t)tok * TD + base) = o;
}

// ---------------- launch ----------------
extern "C" void kernel_launch(void* const* d_in, const int* in_sizes, int n_in,
                              void* d_out, int out_size)
{
    const float* x_l   = (const float*)d_in[0];
    const float* x_r   = (const float*)d_in[1];
    const float* cent  = (const float*)d_in[2];
    const float* projW = (const float*)d_in[3];
    const float* projb = (const float*)d_in[4];
    const float* eW    = (const float*)d_in[5];
    const float* eB    = (const float*)d_in[6];
    const float* lwl   = (const float*)d_in[7];
    const float* lbl   = (const float*)d_in[8];
    const float* lwr   = (const float*)d_in[9];
    const float* lbr   = (const float*)d_in[10];
    float* out = (float*)d_out;

    zero_cnt_kernel<<<1, NE>>>();
    router_kernel<<<NTOK / TPC, 256>>>(x_l, x_r, cent, projW, projb);
    scan_kernel<<<1, NE>>>();
    dim3 g(192, NT);
    expert_gemm_kernel<<<g, 256>>>(x_l, x_r, eW, eB);
    ln_kernel<<<2 * NTOK, 128>>>(x_l, x_r, lwl, lbl, lwr, lbr, out);
}

// round 15
// speedup vs baseline: 3.0156x; 1.0460x over previous
#include <cuda_runtime.h>
#include <cuda_bf16.h>

// ---------------- problem constants ----------------
#define BSZ   8
#define NC    128
#define TD    512
#define EDIM  64
#define NE    128
#define NTOK  (BSZ*NC)     // 1024 tokens
#define T2    (2*TD)       // 1024 concat dim

// ---------------- GEMM tiling ----------------
#define BN 128             // n-columns per CTA
#define NT (TD/BN)         // 4 n-tiles
#define KC 64              // k-tile
#define MC 32              // m rows per work item
#define NKT (TD/KC)        // 8 k-tiles
#define PITCH 36           // smem row pitch in u32 units (32 data + 4 pad)
#define MAXW 256           // max work items

// ---------------- device scratch (no allocation allowed) ----------------
__device__ int   g_cnt[NE];
__device__ int   g_list[NE][NTOK];          // packed token*2 + slot
__device__ int   g_work[MAXW];              // expert | (m-slice << 16)
__device__ int   g_nwork;
__device__ float g_part[4][NTOK][TD];       // [slot*2+stream][token][t]  (8 MB)

// ---------------- helpers ----------------
__device__ __forceinline__ unsigned s2u(const void* p) {
    return (unsigned)__cvta_generic_to_shared(p);
}
__device__ __forceinline__ void ldsm4(unsigned* r, unsigned addr) {
    asm volatile("ldmatrix.sync.aligned.m8n8.x4.shared.b16 {%0,%1,%2,%3},[%4];"
                 : "=r"(r[0]), "=r"(r[1]), "=r"(r[2]), "=r"(r[3]) : "r"(addr));
}
__device__ __forceinline__ void mma16816(float* d, const unsigned* a, const unsigned* b) {
    asm volatile("mma.sync.aligned.m16n8k16.row.col.f32.bf16.bf16.f32 "
                 "{%0,%1,%2,%3},{%4,%5,%6,%7},{%8,%9},{%0,%1,%2,%3};"
                 : "+f"(d[0]), "+f"(d[1]), "+f"(d[2]), "+f"(d[3])
                 : "r"(a[0]), "r"(a[1]), "r"(a[2]), "r"(a[3]), "r"(b[0]), "r"(b[1]));
}
// split fp32 pair -> packed bf16x2 hi + lo (2-term expansion)
__device__ __forceinline__ void split2(float v0, float v1, unsigned& h, unsigned& l) {
    __nv_bfloat162 hb;
    hb.x = __float2bfloat16(v0);
    hb.y = __float2bfloat16(v1);
    h = *reinterpret_cast<unsigned*>(&hb);
    float r0 = v0 - __bfloat162float(hb.x);
    float r1 = v1 - __bfloat162float(hb.y);
    __nv_bfloat162 lb;
    lb.x = __float2bfloat16(r0);
    lb.y = __float2bfloat16(r1);
    l = *reinterpret_cast<unsigned*>(&lb);
}

// ---------------- kernel 0: zero per-expert counters ----------------
__global__ void zero_cnt_kernel() { g_cnt[threadIdx.x] = 0; }

// ---------------- kernel 1: router, 8 tokens/CTA, pipelined projW --------
// s_e = (x @ projW^T + projb) . centers[e]/||centers[e]||
// x_proj L2-norm is a positive per-token scalar (order-preserving) and the
// reference's token-level mask makes each selected expert's combine weight
// exactly 1.0, so only the top-2 indices matter.
#define TPC 8
__global__ __launch_bounds__(256) void router_kernel(
    const float* __restrict__ x_l, const float* __restrict__ x_r,
    const float* __restrict__ centers,
    const float* __restrict__ projW, const float* __restrict__ projb)
{
    __shared__ float xs[TPC][T2];      // 32 KB
    __shared__ float wt[2][2][T2];     // 16 KB ping-pong (2 rows per chunk)
    __shared__ float ps[TPC][EDIM];    // 2 KB
    __shared__ float ss[TPC][NE];      // 4 KB
    int tok0 = blockIdx.x * TPC;
    int tid = threadIdx.x;
    int warp = tid >> 5, lane = tid & 31;

    // load 8 token rows (both streams) vectorized
    {
        int h = tid >> 7, i = tid & 127;   // 128 float4 per stream-row
        #pragma unroll
        for (int t = 0; t < TPC; ++t) {
            const float* src = (h ? x_r : x_l) + (size_t)(tok0 + t) * TD;
            reinterpret_cast<float4*>(&xs[t][h * TD])[i] =
                reinterpret_cast<const float4*>(src)[i];
        }
    }

    // prologue: stage chunk 0
    {
        const float4* src = reinterpret_cast<const float4*>(projW);
        float4 a = src[tid], b = src[tid + 256];
        reinterpret_cast<float4*>(wt[0])[tid]       = a;
        reinterpret_cast<float4*>(wt[0])[tid + 256] = b;
    }
    __syncthreads();

    for (int jc = 0; jc < 32; ++jc) {
        int p = jc & 1;
        // prefetch next chunk into regs (overlaps with compute)
        float4 nxa, nxb;
        if (jc + 1 < 32) {
            const float4* src = reinterpret_cast<const float4*>(projW + (size_t)((jc + 1) * 2) * T2);
            nxa = src[tid];
            nxb = src[tid + 256];
        }
        int t = warp;   // warp <-> token
        #pragma unroll
        for (int jj = 0; jj < 2; ++jj) {
            float s = 0.f;
            #pragma unroll
            for (int kk = 0; kk < 8; ++kk) {
                int k = (kk * 32 + lane) * 4;
                float4 a = *reinterpret_cast<const float4*>(&xs[t][k]);
                float4 b = *reinterpret_cast<const float4*>(&wt[p][jj][k]);
                s += a.x * b.x + a.y * b.y + a.z * b.z + a.w * b.w;
            }
            #pragma unroll
            for (int o = 16; o; o >>= 1) s += __shfl_xor_sync(0xffffffffu, s, o);
            if (lane == 0) ps[t][jc * 2 + jj] = s + projb[jc * 2 + jj];
        }
        if (jc + 1 < 32) {
            reinterpret_cast<float4*>(wt[p ^ 1])[tid]       = nxa;
            reinterpret_cast<float4*>(wt[p ^ 1])[tid + 256] = nxb;
        }
        __syncthreads();
    }

    // 1024 (token, expert) scores over 256 threads, 4 rounds
    #pragma unroll
    for (int r = 0; r < 4; ++r) {
        int idx = tid + 256 * r;
        int t = idx >> 7, e = idx & 127;
        const float* c = centers + (size_t)e * EDIM;
        float s = 0.f, n = 0.f;
        #pragma unroll 8
        for (int j = 0; j < EDIM; ++j) { float cv = c[j]; s += ps[t][j] * cv; n += cv * cv; }
        ss[t][e] = s * rsqrtf(fmaxf(n, 1e-24f));
    }
    __syncthreads();

    // warp-parallel top-2: warp t reduces token t's 128 scores.
    // tie-break: smaller index wins (matches jax.lax.top_k first-index).
    {
        int t = warp;
        float v[4]; int id[4];
        #pragma unroll
        for (int q = 0; q < 4; ++q) { id[q] = lane + 32 * q; v[q] = ss[t][id[q]]; }
        // local argmax over 4
        float bv_ = v[0]; int bi = id[0];
        #pragma unroll
        for (int q = 1; q < 4; ++q)
            if (v[q] > bv_ || (v[q] == bv_ && id[q] < bi)) { bv_ = v[q]; bi = id[q]; }
        float m1v = bv_; int m1i = bi;
        #pragma unroll
        for (int o = 16; o; o >>= 1) {
            float ov = __shfl_xor_sync(0xffffffffu, m1v, o);
            int   oi = __shfl_xor_sync(0xffffffffu, m1i, o);
            if (ov > m1v || (ov == m1v && oi < m1i)) { m1v = ov; m1i = oi; }
        }
        // second max: invalidate e0, redo local + warp reduce
        bv_ = -3.4e38f; bi = 0x7fffffff;
        #pragma unroll
        for (int q = 0; q < 4; ++q)
            if (id[q] != m1i && (v[q] > bv_ || (v[q] == bv_ && id[q] < bi))) { bv_ = v[q]; bi = id[q]; }
        float m2v = bv_; int m2i = bi;
        #pragma unroll
        for (int o = 16; o; o >>= 1) {
            float ov = __shfl_xor_sync(0xffffffffu, m2v, o);
            int   oi = __shfl_xor_sync(0xffffffffu, m2i, o);
            if (ov > m2v || (ov == m2v && oi < m2i)) { m2v = ov; m2i = oi; }
        }
        if (lane == 0) {
            int tok = tok0 + t;
            int p0 = atomicAdd(&g_cnt[m1i], 1);
            g_list[m1i][p0] = tok * 2 + 0;
            int p1 = atomicAdd(&g_cnt[m2i], 1);
            g_list[m2i][p1] = tok * 2 + 1;
        }
    }
}

// ---------------- kernel 1.5: build balanced work queue ----------------
__global__ void scan_kernel() {
    __shared__ int ws[4];
    int e = threadIdx.x;               // 128 threads
    int c = (2 * g_cnt[e] + MC - 1) / MC;
    int lane = e & 31, w = e >> 5;
    int v = c;
    #pragma unroll
    for (int o = 1; o < 32; o <<= 1) {
        int t = __shfl_up_sync(0xffffffffu, v, o);
        if (lane >= o) v += t;
    }
    if (lane == 31) ws[w] = v;
    __syncthreads();
    int add = 0;
    for (int i = 0; i < w; ++i) add += ws[i];
    int excl = add + v - c;
    for (int i = 0; i < c; ++i)
        g_work[excl + i] = e | (i << 16);
    if (e == NE - 1) g_nwork = excl + c;
}

// ---------------- kernel 2: grouped GEMM via bf16-split HMMA ------------
// CTA (wi, nt): 32 gathered rows x 128 n-cols x K=512.
// W and x split into bf16 hi+lo planes in smem; products hh + hl + lh give
// ~fp32 accuracy. Frags fed by ldmatrix (conflict-free, PITCH = 36 u32).
// NOTE: uncapped launch bounds — R11's (256,4) regs=64 cap cost ILP and
// regressed the GEMM 69->81us; R8's regs=77 @ 3 CTAs/SM is faster.
__global__ __launch_bounds__(256) void expert_gemm_kernel(
    const float* __restrict__ x_l, const float* __restrict__ x_r,
    const float* __restrict__ eW,  const float* __restrict__ eB)
{
    __shared__ unsigned Whi[BN * PITCH];   // 18.4 KB each
    __shared__ unsigned Wlo[BN * PITCH];
    __shared__ unsigned Xhi[MC * PITCH];   // 4.6 KB each
    __shared__ unsigned Xlo[MC * PITCH];

    int wi = blockIdx.x;
    if (wi >= g_nwork) return;
    int item = g_work[wi];
    int e  = item & 0xffff;
    int mp = (item >> 16) * MC;
    int nt = blockIdx.y;
    int cnt = g_cnt[e];
    int rows = 2 * cnt;

    int tid = threadIdx.x, lane = tid & 31, warp = tid >> 5;
    int mhalf = (warp & 1) * 16;       // warp's 16-row half
    int ng    = (warp >> 1) * 32;      // warp's 32-col group
    int N0    = nt * BN;
    const float* We = eW + (size_t)e * TD * TD + (size_t)N0 * TD;

    int g  = lane >> 2;                // accum row group 0..7
    int t2 = (lane & 3) * 2;           // accum col pair

    // bias (per n-tile float2)
    float2 bv[4];
    #pragma unroll
    for (int q = 0; q < 4; ++q)
        bv[q] = *reinterpret_cast<const float2*>(eB + (size_t)e * TD + N0 + ng + q * 8 + t2);

    // row metadata for this thread's 2 output rows
    int tokr[2], dsel[2], valr[2];
    #pragma unroll
    for (int i = 0; i < 2; ++i) {
        int r = mp + mhalf + g + i * 8;
        valr[i] = (r < rows);
        int rr = valr[i] ? r : 0;
        int entry = (rr < cnt) ? rr : rr - cnt;
        int str = (rr < cnt) ? 0 : 1;
        int packed = g_list[e][entry];
        tokr[i] = packed >> 1;
        dsel[i] = (packed & 1) * 2 + str;
    }

    // x loader (row xm of slice, 8 k per thread)
    int xm = tid >> 3, xk8 = (tid & 7) * 8;
    const float* xsrc = nullptr;
    {
        int lr = mp + xm;
        if (lr < rows) {
            int entry = (lr < cnt) ? lr : lr - cnt;
            const float* base = (lr < cnt) ? x_l : x_r;
            xsrc = base + (size_t)(g_list[e][entry] >> 1) * TD;
        }
    }
    // W loader (rows wn+16i, 4 k per float4)
    int wn = tid >> 4, wk4 = (tid & 15) * 4;

    float acc[4][4];
    #pragma unroll
    for (int q = 0; q < 4; ++q)
        #pragma unroll
        for (int i = 0; i < 4; ++i) acc[q][i] = 0.f;

    // ldmatrix lane offsets (u32 units)
    unsigned aOffU  = (unsigned)((mhalf + (lane & 15)) * PITCH + ((lane >> 4) & 1) * 4);
    unsigned brow   = (unsigned)(ng + ((lane >> 4) & 1) * 8 + (lane & 7));
    unsigned bkU    = (unsigned)(((lane >> 3) & 1) * 4);
    unsigned bOffU0 = brow * PITCH + bkU;
    unsigned bOffU1 = (brow + 16) * PITCH + bkU;

    unsigned XhiA = s2u(Xhi), XloA = s2u(Xlo), WhiA = s2u(Whi), WloA = s2u(Wlo);

    for (int kt = 0; kt < NKT; ++kt) {
        int k0 = kt * KC;
        __syncthreads();
        // ---- stage W tile as bf16 hi/lo planes ----
        #pragma unroll
        for (int i = 0; i < 8; ++i) {
            int n = wn + 16 * i;
            float4 v = *reinterpret_cast<const float4*>(We + (size_t)n * TD + k0 + wk4);
            unsigned h0, l0, h1, l1;
            split2(v.x, v.y, h0, l0);
            split2(v.z, v.w, h1, l1);
            int u = n * PITCH + (wk4 >> 1);
            *reinterpret_cast<uint2*>(&Whi[u]) = make_uint2(h0, h1);
            *reinterpret_cast<uint2*>(&Wlo[u]) = make_uint2(l0, l1);
        }
        // ---- stage x tile ----
        #pragma unroll
        for (int i = 0; i < 2; ++i) {
            float4 v = xsrc ? *reinterpret_cast<const float4*>(xsrc + k0 + xk8 + i * 4)
                            : make_float4(0.f, 0.f, 0.f, 0.f);
            unsigned h0, l0, h1, l1;
            split2(v.x, v.y, h0, l0);
            split2(v.z, v.w, h1, l1);
            int u = xm * PITCH + ((xk8 + i * 4) >> 1);
            *reinterpret_cast<uint2*>(&Xhi[u]) = make_uint2(h0, h1);
            *reinterpret_cast<uint2*>(&Xlo[u]) = make_uint2(l0, l1);
        }
        __syncthreads();
        // ---- 4 k16-chunks: ldmatrix + 12 HMMA each ----
        #pragma unroll
        for (int c = 0; c < 4; ++c) {
            unsigned cu4 = (unsigned)(c * 8) * 4u;   // byte offset of chunk
            unsigned ahi[4], alo[4], b0h[4], b1h[4], b0l[4], b1l[4];
            ldsm4(ahi, XhiA + (aOffU * 4u) + cu4);
            ldsm4(alo, XloA + (aOffU * 4u) + cu4);
            ldsm4(b0h, WhiA + (bOffU0 * 4u) + cu4);
            ldsm4(b1h, WhiA + (bOffU1 * 4u) + cu4);
            ldsm4(b0l, WloA + (bOffU0 * 4u) + cu4);
            ldsm4(b1l, WloA + (bOffU1 * 4u) + cu4);
            // n-tiles 0..3: (b0h[0:2], b0h[2:4], b1h[0:2], b1h[2:4])
            mma16816(acc[0], ahi, b0h + 0);
            mma16816(acc[1], ahi, b0h + 2);
            mma16816(acc[2], ahi, b1h + 0);
            mma16816(acc[3], ahi, b1h + 2);
            mma16816(acc[0], ahi, b0l + 0);
            mma16816(acc[1], ahi, b0l + 2);
            mma16816(acc[2], ahi, b1l + 0);
            mma16816(acc[3], ahi, b1l + 2);
            mma16816(acc[0], alo, b0h + 0);
            mma16816(acc[1], alo, b0h + 2);
            mma16816(acc[2], alo, b1h + 0);
            mma16816(acc[3], alo, b1h + 2);
        }
    }

    // ---- epilogue: float2 STG per (row, n-tile) ----
    #pragma unroll
    for (int q = 0; q < 4; ++q) {
        int n = N0 + ng + q * 8 + t2;
        if (valr[0]) {
            float2 o = make_float2(acc[q][0] + bv[q].x, acc[q][1] + bv[q].y);
            *reinterpret_cast<float2*>(&g_part[dsel[0]][tokr[0]][n]) = o;
        }
        if (valr[1]) {
            float2 o = make_float2(acc[q][2] + bv[q].x, acc[q][3] + bv[q].y);
            *reinterpret_cast<float2*>(&g_part[dsel[1]][tokr[1]][n]) = o;
        }
    }
}

// ---------------- kernel 3: combine slots + LayerNorm + residual --------
__global__ __launch_bounds__(128) void ln_kernel(
    const float* __restrict__ x_l, const float* __restrict__ x_r,
    const float* __restrict__ lw_l, const float* __restrict__ lb_l,
    const float* __restrict__ lw_r, const float* __restrict__ lb_r,
    float* __restrict__ out)
{
    __shared__ float red[8];
    int bid = blockIdx.x;
    int stream = bid >> 10;            // NTOK = 1024
    int tok = bid & (NTOK - 1);
    int tid = threadIdx.x;

    const float* p0 = g_part[0 * 2 + stream][tok];
    const float* p1 = g_part[1 * 2 + stream][tok];
    const float* xr = (stream ? x_r : x_l) + (size_t)tok * TD;
    const float* w  = stream ? lw_r : lw_l;
    const float* b  = stream ? lb_r : lb_l;

    int base = tid * 4;
    float4 a = *reinterpret_cast<const float4*>(p0 + base);
    float4 c = *reinterpret_cast<const float4*>(p1 + base);
    float v0 = a.x + c.x, v1 = a.y + c.y, v2 = a.z + c.z, v3 = a.w + c.w;
    float s1 = v0 + v1 + v2 + v3;
    float s2 = v0 * v0 + v1 * v1 + v2 * v2 + v3 * v3;
    #pragma unroll
    for (int o = 16; o; o >>= 1) {
        s1 += __shfl_xor_sync(0xffffffffu, s1, o);
        s2 += __shfl_xor_sync(0xffffffffu, s2, o);
    }
    int warp = tid >> 5, lane = tid & 31;
    if (lane == 0) { red[warp] = s1; red[4 + warp] = s2; }
    __syncthreads();
    float S1 = red[0] + red[1] + red[2] + red[3];
    float S2 = red[4] + red[5] + red[6] + red[7];
    float mu  = S1 * (1.f / TD);
    float var = S2 * (1.f / TD) - mu * mu;
    float rs  = rsqrtf(fmaxf(var, 0.f) + 1e-5f);

    float4 wv = *reinterpret_cast<const float4*>(w + base);
    float4 bv = *reinterpret_cast<const float4*>(b + base);
    float4 xv = *reinterpret_cast<const float4*>(xr + base);
    float4 o;
    o.x = (v0 - mu) * rs * wv.x + bv.x + xv.x;
    o.y = (v1 - mu) * rs * wv.y + bv.y + xv.y;
    o.z = (v2 - mu) * rs * wv.z + bv.z + xv.z;
    o.w = (v3 - mu) * rs * wv.w + bv.w + xv.w;
    *reinterpret_cast<float4*>(out + (size_t)stream * NTOK * TD + (size_t)tok * TD + base) = o;
}

// ---------------- launch ----------------
extern "C" void kernel_launch(void* const* d_in, const int* in_sizes, int n_in,
                              void* d_out, int out_size)
{
    const float* x_l   = (const float*)d_in[0];
    const float* x_r   = (const float*)d_in[1];
    const float* cent  = (const float*)d_in[2];
    const float* projW = (const float*)d_in[3];
    const float* projb = (const float*)d_in[4];
    const float* eW    = (const float*)d_in[5];
    const float* eB    = (const float*)d_in[6];
    const float* lwl   = (const float*)d_in[7];
    const float* lbl   = (const float*)d_in[8];
    const float* lwr   = (const float*)d_in[9];
    const float* lbr   = (const float*)d_in[10];
    float* out = (float*)d_out;

    zero_cnt_kernel<<<1, NE>>>();
    router_kernel<<<NTOK / TPC, 256>>>(x_l, x_r, cent, projW, projb);
    scan_kernel<<<1, NE>>>();
    dim3 g(192, NT);
    expert_gemm_kernel<<<g, 256>>>(x_l, x_r, eW, eB);
    ln_kernel<<<2 * NTOK, 128>>>(x_l, x_r, lwl, lbl, lwr, lbr, out);
}